// round 4
// baseline (speedup 1.0000x reference)
#include <cuda_runtime.h>
#include <cuda_bf16.h>
#include <cstdint>

#define TOKENS   8192
#define DIM      512
#define FDIM     128
#define NLEAF    8
#define BM       128
#define MAXTILES 64

// ---------------- scratch ----------------
__device__ int g_count[NLEAF];
__device__ int g_list[NLEAF * TOKENS];
// W1 transposed+interleaved+split: [leaf][n=256][k=512]; n=2f -> w1a col f, n=2f+1 -> w1b col f
__device__ __nv_bfloat16 g_w1t_hi[NLEAF * 256 * 512];
__device__ __nv_bfloat16 g_w1t_lo[NLEAF * 256 * 512];
// W2 transposed+split: [leaf][n=512][k=128]
__device__ __nv_bfloat16 g_w2t_hi[NLEAF * 512 * 128];
__device__ __nv_bfloat16 g_w2t_lo[NLEAF * 512 * 128];

__device__ __forceinline__ uint32_t smem_u32(const void* p) {
    uint32_t a;
    asm("{ .reg .u64 t; cvta.to.shared.u64 t, %1; cvt.u32.u64 %0, t; }" : "=r"(a) : "l"(p));
    return a;
}
__device__ __forceinline__ uint32_t sw128(uint32_t off) { return off ^ ((off >> 3) & 0x70); }

__device__ __forceinline__ void split_bf16(float v, __nv_bfloat16& h, __nv_bfloat16& l) {
    h = __float2bfloat16(v);
    l = __float2bfloat16(v - __bfloat162float(h));
}

#define LDSM4(r, a)                                                                   \
    asm volatile("ldmatrix.sync.aligned.m8n8.x4.shared.b16 {%0,%1,%2,%3}, [%4];"     \
        : "=r"((r)[0]), "=r"((r)[1]), "=r"((r)[2]), "=r"((r)[3]) : "r"(a))

__device__ __forceinline__ void mma_bf16(float* d, const uint32_t* a, uint32_t b0, uint32_t b1) {
    asm volatile(
        "mma.sync.aligned.m16n8k16.row.col.f32.bf16.bf16.f32 "
        "{%0,%1,%2,%3},{%4,%5,%6,%7},{%8,%9},{%0,%1,%2,%3};"
        : "+f"(d[0]), "+f"(d[1]), "+f"(d[2]), "+f"(d[3])
        : "r"(a[0]), "r"(a[1]), "r"(a[2]), "r"(a[3]), "r"(b0), "r"(b1));
}

// ---------------- prep: coalesced transpose + bf16 split ----------------
__global__ void prep_w1(const float* __restrict__ w1a, const float* __restrict__ w1b) {
    if (blockIdx.x == 0 && blockIdx.y == 0 && blockIdx.z == 0 && threadIdx.x < NLEAF)
        g_count[threadIdx.x] = 0;
    const int leaf = blockIdx.z, kt = blockIdx.y, ft = blockIdx.x;  // kt<16, ft<4
    __shared__ float ta[32][33], tb[32][33];
    const int tid = threadIdx.x;
    {   // load 32k x 32f tile, coalesced
        int r = tid >> 3, cq = tid & 7;
        size_t src = ((size_t)leaf * 512 + kt * 32 + r) * 128 + ft * 32 + cq * 4;
        float4 va = *(const float4*)(w1a + src);
        float4 vb = *(const float4*)(w1b + src);
        ta[r][cq*4+0]=va.x; ta[r][cq*4+1]=va.y; ta[r][cq*4+2]=va.z; ta[r][cq*4+3]=va.w;
        tb[r][cq*4+0]=vb.x; tb[r][cq*4+1]=vb.y; tb[r][cq*4+2]=vb.z; tb[r][cq*4+3]=vb.w;
    }
    __syncthreads();
    {   // write 64 interleaved n-rows x 32 k, coalesced-ish (16B per thread)
        int n = tid >> 2, kq = tid & 3;          // n<64, kq<4
        int f = n >> 1, side = n & 1;
        union { __nv_bfloat16 b[8]; uint4 u; } h8, l8;
        #pragma unroll
        for (int j = 0; j < 8; j++) {
            float v = side ? tb[kq * 8 + j][f] : ta[kq * 8 + j][f];
            split_bf16(v, h8.b[j], l8.b[j]);
        }
        size_t orow = ((size_t)leaf * 256 + ft * 64 + n) * 512 + kt * 32 + kq * 8;
        *(uint4*)(g_w1t_hi + orow) = h8.u;
        *(uint4*)(g_w1t_lo + orow) = l8.u;
    }
}

__global__ void prep_w2(const float* __restrict__ w2) {
    const int leaf = blockIdx.z, kt = blockIdx.y, dt = blockIdx.x;  // kt<4, dt<16
    __shared__ float t[32][33];
    const int tid = threadIdx.x;
    {
        int r = tid >> 3, cq = tid & 7;
        size_t src = ((size_t)leaf * 128 + kt * 32 + r) * 512 + dt * 32 + cq * 4;
        float4 v = *(const float4*)(w2 + src);
        t[r][cq*4+0]=v.x; t[r][cq*4+1]=v.y; t[r][cq*4+2]=v.z; t[r][cq*4+3]=v.w;
    }
    __syncthreads();
    {
        int n = tid >> 3, kq = tid & 7;          // n<32, kq<8 -> 4 k each
        union { __nv_bfloat16 b[4]; uint2 u; } h4, l4;
        #pragma unroll
        for (int j = 0; j < 4; j++) split_bf16(t[kq * 4 + j][n], h4.b[j], l4.b[j]);
        size_t orow = ((size_t)leaf * 512 + dt * 32 + n) * 128 + kt * 32 + kq * 4;
        *(uint2*)(g_w2t_hi + orow) = h4.u;
        *(uint2*)(g_w2t_lo + orow) = l4.u;
    }
}

// ---------------- routing (known-good) ----------------
__device__ __forceinline__ float warp_sum(float v) {
    #pragma unroll
    for (int o = 16; o > 0; o >>= 1) v += __shfl_xor_sync(0xFFFFFFFFu, v, o);
    return v;
}

__global__ void route_kernel(const float* __restrict__ x,
                             const float* __restrict__ wn0, const float* __restrict__ bn0,
                             const float* __restrict__ wn1, const float* __restrict__ bn1,
                             const float* __restrict__ wn2, const float* __restrict__ bn2)
{
    int gwarp = (blockIdx.x * blockDim.x + threadIdx.x) >> 5;
    int lane  = threadIdx.x & 31;
    if (gwarp >= TOKENS) return;

    const float4* xr4 = (const float4*)(x + (size_t)gwarp * DIM);
    float4 xv[4];
    #pragma unroll
    for (int i = 0; i < 4; i++) xv[i] = xr4[lane + i * 32];

    float s = 0.f;
    #pragma unroll
    for (int i = 0; i < 4; i++) {
        int base = (lane + i * 32) * 4;
        s += xv[i].x * wn0[base + 0] + xv[i].y * wn0[base + 1]
           + xv[i].z * wn0[base + 2] + xv[i].w * wn0[base + 3];
    }
    s = warp_sum(s) + bn0[0];
    int node = (s > 0.f) ? 0 : 1;

    s = 0.f;
    #pragma unroll
    for (int i = 0; i < 4; i++) {
        int base = (lane + i * 32) * 4;
        s += xv[i].x * wn1[(base + 0) * 2 + node] + xv[i].y * wn1[(base + 1) * 2 + node]
           + xv[i].z * wn1[(base + 2) * 2 + node] + xv[i].w * wn1[(base + 3) * 2 + node];
    }
    s = warp_sum(s) + bn1[node];
    node = node * 2 + ((s > 0.f) ? 0 : 1);

    s = 0.f;
    #pragma unroll
    for (int i = 0; i < 4; i++) {
        int base = (lane + i * 32) * 4;
        s += xv[i].x * wn2[(base + 0) * 4 + node] + xv[i].y * wn2[(base + 1) * 4 + node]
           + xv[i].z * wn2[(base + 2) * 4 + node] + xv[i].w * wn2[(base + 3) * 4 + node];
    }
    s = warp_sum(s) + bn2[node];
    int leaf = node * 2 + ((s > 0.f) ? 0 : 1);

    if (lane == 0) {
        int pos = atomicAdd(&g_count[leaf], 1);
        g_list[leaf * TOKENS + pos] = gwarp;
    }
}

// ---------------- SMEM layout ----------------
#define SM_ROWTOK  0        // 512B
#define SM_B1A     512      // 512B
#define SM_B1B     1024     // 512B
#define SM_B2      1536     // 2KB
#define SM_XHI     4096     // 16KB  X chunk [128][64] bf16 SW128 (128B rows)
#define SM_XLO     20480    // 16KB
#define SM_WHI     36864    // 32KB  W chunk [256][64] bf16 SW128
#define SM_WLO     69632    // 32KB
#define SM_HHI0    102400   // 16KB  H (k 0..63) hi
#define SM_HLO0    118784
#define SM_HHI1    135168   //       H (k 64..127)
#define SM_HLO1    151552
#define SMEM_TOTAL 167936

// ---------------- fused leaf FFN: bf16-split mma.sync ----------------
__global__ void __launch_bounds__(256, 1)
ffn_kernel(const float* __restrict__ x,
           const float* __restrict__ b1a, const float* __restrict__ b1b,
           const float* __restrict__ b2,  float* __restrict__ out)
{
    extern __shared__ char smem[];
    const uint32_t sb = smem_u32(smem);
    const int tid  = threadIdx.x;
    const int wid  = tid >> 5;
    const int lane = tid & 31;

    const int leaf  = blockIdx.x;
    const int cnt   = g_count[leaf];
    const int start = blockIdx.y * BM;
    if (start >= cnt) return;
    const int rows = min(BM, cnt - start);
    const int* list = g_list + leaf * TOKENS + start;

    int* rowTok = (int*)(smem + SM_ROWTOK);
    if (tid < BM) rowTok[tid] = list[min(tid, rows - 1)];
    {
        float* sB1a = (float*)(smem + SM_B1A);
        float* sB1b = (float*)(smem + SM_B1B);
        float* sB2  = (float*)(smem + SM_B2);
        if (tid < FDIM) { sB1a[tid] = b1a[leaf * FDIM + tid]; sB1b[tid] = b1b[leaf * FDIM + tid]; }
        for (int i = tid; i < DIM; i += 256) sB2[i] = b2[leaf * DIM + i];
    }
    __syncthreads();

    const int wm = wid & 3;        // m-block: rows 32*wm .. +31
    const int wn = wid >> 2;       // n-block: cols 128*wn .. +127
    const int gid = lane >> 2, tig = lane & 3;

    // ldmatrix lane-address components
    const int a_row = lane & 15;                               // row within m16 pair
    const int a_kad = (lane & 16) >> 1;                        // +8 k for matrices 2,3
    const int b_row = (lane & 7) | ((lane >> 1) & 8);          // n within n16
    const int b_kad = lane & 8;                                // +8 k for matrices 1,3

    const int r_x = tid >> 1, half_x = tid & 1;                // X loader mapping

    // ================= GEMM1: C1[128,256] = X @ W1t^T (3 split passes) =================
    float acc[2][16][4];
    #pragma unroll
    for (int s = 0; s < 2; s++)
        #pragma unroll
        for (int t = 0; t < 16; t++)
            #pragma unroll
            for (int j = 0; j < 4; j++) acc[s][t][j] = 0.f;

    for (int c = 0; c < 8; c++) {
        const int k0 = c * 64;
        {   // X chunk: split fp32 -> bf16 hi/lo, SW128 store
            const int tok = rowTok[r_x];
            const float4* src = (const float4*)(x + (size_t)tok * DIM + k0 + half_x * 32);
            #pragma unroll
            for (int g = 0; g < 4; g++) {
                float4 a = src[g * 2], b = src[g * 2 + 1];
                float va[8] = { a.x, a.y, a.z, a.w, b.x, b.y, b.z, b.w };
                union { __nv_bfloat16 b[8]; uint4 u; } h8, l8;
                #pragma unroll
                for (int j = 0; j < 8; j++) split_bf16(va[j], h8.b[j], l8.b[j]);
                uint32_t sw = sw128((uint32_t)(r_x * 128 + (half_x * 32 + g * 8) * 2));
                *(uint4*)(smem + SM_XHI + sw) = h8.u;
                *(uint4*)(smem + SM_XLO + sw) = l8.u;
            }
        }
        {   // W1 chunk: row tid of 256, 128B
            const __nv_bfloat16* sh = g_w1t_hi + ((size_t)(leaf * 256 + tid)) * DIM + k0;
            const __nv_bfloat16* sl = g_w1t_lo + ((size_t)(leaf * 256 + tid)) * DIM + k0;
            #pragma unroll
            for (int g = 0; g < 8; g++) {
                uint32_t sw = sw128((uint32_t)(tid * 128 + g * 16));
                *(uint4*)(smem + SM_WHI + sw) = *(const uint4*)(sh + g * 8);
                *(uint4*)(smem + SM_WLO + sw) = *(const uint4*)(sl + g * 8);
            }
        }
        __syncthreads();
        #pragma unroll
        for (int pass = 0; pass < 3; pass++) {
            const uint32_t abase = sb + ((pass == 2) ? SM_XLO : SM_XHI);
            const uint32_t bbase = sb + ((pass == 1) ? SM_WLO : SM_WHI);
            #pragma unroll
            for (int kof = 0; kof < 64; kof += 16) {
                uint32_t afr[2][4];
                #pragma unroll
                for (int s = 0; s < 2; s++)
                    LDSM4(afr[s], abase + sw128((uint32_t)((32 * wm + 16 * s + a_row) * 128
                                                           + (kof + a_kad) * 2)));
                #pragma unroll
                for (int nt = 0; nt < 8; nt++) {
                    uint32_t bfr[4];
                    LDSM4(bfr, bbase + sw128((uint32_t)((128 * wn + 16 * nt + b_row) * 128
                                                        + (kof + b_kad) * 2)));
                    #pragma unroll
                    for (int s = 0; s < 2; s++) {
                        mma_bf16(acc[s][2 * nt],     afr[s], bfr[0], bfr[1]);
                        mma_bf16(acc[s][2 * nt + 1], afr[s], bfr[2], bfr[3]);
                    }
                }
            }
        }
        __syncthreads();
    }

    // ================= epilogue1: gate adjacent (a,b) cols -> H bf16 hi/lo =================
    {
        const float* sB1a = (const float*)(smem + SM_B1A);
        const float* sB1b = (const float*)(smem + SM_B1B);
        #pragma unroll
        for (int s = 0; s < 2; s++) {
            const int r0 = 32 * wm + 16 * s + gid;
            #pragma unroll
            for (int t = 0; t < 16; t++) {
                const int f = 64 * wn + 4 * t + tig;      // interleave: col 2f=a, 2f+1=b
                const float ba = sB1a[f], bb = sB1b[f];
                const float h0 = (acc[s][t][0] + ba) * (acc[s][t][1] + bb);
                const float h1 = (acc[s][t][2] + ba) * (acc[s][t][3] + bb);
                char* hh = smem + ((f < 64) ? SM_HHI0 : SM_HHI1);
                char* hl = smem + ((f < 64) ? SM_HLO0 : SM_HLO1);
                const uint32_t o0 = sw128((uint32_t)(r0 * 128 + (f & 63) * 2));
                const uint32_t o1 = sw128((uint32_t)((r0 + 8) * 128 + (f & 63) * 2));
                __nv_bfloat16 hh0, hl0, hh1, hl1;
                split_bf16(h0, hh0, hl0);
                split_bf16(h1, hh1, hl1);
                *(__nv_bfloat16*)(hh + o0) = hh0;  *(__nv_bfloat16*)(hl + o0) = hl0;
                *(__nv_bfloat16*)(hh + o1) = hh1;  *(__nv_bfloat16*)(hl + o1) = hl1;
            }
        }
    }
    __syncthreads();

    // ================= GEMM2: Y[128,512] = H @ W2t^T, two N-halves =================
    const float* sB2 = (const float*)(smem + SM_B2);
    for (int nh = 0; nh < 2; nh++) {
        float acc2[2][16][4];
        #pragma unroll
        for (int s = 0; s < 2; s++)
            #pragma unroll
            for (int t = 0; t < 16; t++)
                #pragma unroll
                for (int j = 0; j < 4; j++) acc2[s][t][j] = 0.f;

        #pragma unroll
        for (int c2 = 0; c2 < 2; c2++) {
            const int k0 = c2 * 64;
            __syncthreads();   // previous chunk's ldsm done before W overwrite
            {
                const __nv_bfloat16* sh = g_w2t_hi + ((size_t)(leaf * 512 + nh * 256 + tid)) * FDIM + k0;
                const __nv_bfloat16* sl = g_w2t_lo + ((size_t)(leaf * 512 + nh * 256 + tid)) * FDIM + k0;
                #pragma unroll
                for (int g = 0; g < 8; g++) {
                    uint32_t sw = sw128((uint32_t)(tid * 128 + g * 16));
                    *(uint4*)(smem + SM_WHI + sw) = *(const uint4*)(sh + g * 8);
                    *(uint4*)(smem + SM_WLO + sw) = *(const uint4*)(sl + g * 8);
                }
            }
            __syncthreads();
            const uint32_t hhi = sb + (c2 ? SM_HHI1 : SM_HHI0);
            const uint32_t hlo = sb + (c2 ? SM_HLO1 : SM_HLO0);
            #pragma unroll
            for (int pass = 0; pass < 3; pass++) {
                const uint32_t abase = (pass == 2) ? hlo : hhi;
                const uint32_t bbase = sb + ((pass == 1) ? SM_WLO : SM_WHI);
                #pragma unroll
                for (int kof = 0; kof < 64; kof += 16) {
                    uint32_t afr[2][4];
                    #pragma unroll
                    for (int s = 0; s < 2; s++)
                        LDSM4(afr[s], abase + sw128((uint32_t)((32 * wm + 16 * s + a_row) * 128
                                                               + (kof + a_kad) * 2)));
                    #pragma unroll
                    for (int nt = 0; nt < 8; nt++) {
                        uint32_t bfr[4];
                        LDSM4(bfr, bbase + sw128((uint32_t)((128 * wn + 16 * nt + b_row) * 128
                                                            + (kof + b_kad) * 2)));
                        #pragma unroll
                        for (int s = 0; s < 2; s++) {
                            mma_bf16(acc2[s][2 * nt],     afr[s], bfr[0], bfr[1]);
                            mma_bf16(acc2[s][2 * nt + 1], afr[s], bfr[2], bfr[3]);
                        }
                    }
                }
            }
        }

        // epilogue2: bias + direct v2 global stores
        #pragma unroll
        for (int s = 0; s < 2; s++) {
            const int r0 = 32 * wm + 16 * s + gid;
            #pragma unroll
            for (int t = 0; t < 16; t++) {
                const int col = nh * 256 + 128 * wn + 8 * t + 2 * tig;
                const float c0 = sB2[col], c1 = sB2[col + 1];
                if (r0 < rows) {
                    float2 v = { acc2[s][t][0] + c0, acc2[s][t][1] + c1 };
                    *(float2*)(out + (size_t)rowTok[r0] * DIM + col) = v;
                }
                if (r0 + 8 < rows) {
                    float2 v = { acc2[s][t][2] + c0, acc2[s][t][3] + c1 };
                    *(float2*)(out + (size_t)rowTok[r0 + 8] * DIM + col) = v;
                }
            }
        }
    }
}

extern "C" void kernel_launch(void* const* d_in, const int* in_sizes, int n_in,
                              void* d_out, int out_size)
{
    const float* x   = (const float*)d_in[0];
    const float* wn0 = (const float*)d_in[2];
    const float* bn0 = (const float*)d_in[3];
    const float* wn1 = (const float*)d_in[4];
    const float* bn1 = (const float*)d_in[5];
    const float* wn2 = (const float*)d_in[6];
    const float* bn2 = (const float*)d_in[7];
    const float* w1a = (const float*)d_in[8];
    const float* b1a = (const float*)d_in[9];
    const float* w1b = (const float*)d_in[10];
    const float* b1b = (const float*)d_in[11];
    const float* w2  = (const float*)d_in[12];
    const float* b2  = (const float*)d_in[13];
    float* out = (float*)d_out;

    static_assert(SMEM_TOTAL <= 227 * 1024, "smem");
    cudaFuncSetAttribute(ffn_kernel, cudaFuncAttributeMaxDynamicSharedMemorySize, SMEM_TOTAL);

    prep_w1<<<dim3(4, 16, NLEAF), 256>>>(w1a, w1b);     // also zeroes g_count
    prep_w2<<<dim3(16, 4, NLEAF), 256>>>(w2);
    route_kernel<<<(TOKENS * 32) / 256, 256>>>(x, wn0, bn0, wn1, bn1, wn2, bn2);
    dim3 grid(NLEAF, MAXTILES);
    ffn_kernel<<<grid, 256, SMEM_TOTAL>>>(x, b1a, b1b, b2, out);
}

// round 5
// speedup vs baseline: 1.5826x; 1.5826x over previous
#include <cuda_runtime.h>
#include <cuda_bf16.h>
#include <cstdint>

#define TOKENS   8192
#define DIM      512
#define FDIM     128
#define NLEAF    8
#define BM       64
#define MAXTILES 32

// ---------------- scratch ----------------
__device__ int g_count[NLEAF];
__device__ int g_list[NLEAF * TOKENS];
// pre-split activations [tok][512]
__device__ __nv_bfloat16 g_x_hi[TOKENS * DIM];
__device__ __nv_bfloat16 g_x_lo[TOKENS * DIM];
// W1 transposed+interleaved+split: [leaf][n=256][k=512]; n=2f -> w1a col f, n=2f+1 -> w1b col f
__device__ __nv_bfloat16 g_w1t_hi[NLEAF * 256 * 512];
__device__ __nv_bfloat16 g_w1t_lo[NLEAF * 256 * 512];
// W2 transposed+split: [leaf][n=512][k=128]
__device__ __nv_bfloat16 g_w2t_hi[NLEAF * 512 * 128];
__device__ __nv_bfloat16 g_w2t_lo[NLEAF * 512 * 128];

__device__ __forceinline__ uint32_t smem_u32(const void* p) {
    uint32_t a;
    asm("{ .reg .u64 t; cvta.to.shared.u64 t, %1; cvt.u32.u64 %0, t; }" : "=r"(a) : "l"(p));
    return a;
}
__device__ __forceinline__ uint32_t sw128(uint32_t off) { return off ^ ((off >> 3) & 0x70); }

__device__ __forceinline__ void split_bf16(float v, __nv_bfloat16& h, __nv_bfloat16& l) {
    h = __float2bfloat16(v);
    l = __float2bfloat16(v - __bfloat162float(h));
}

__device__ __forceinline__ void cpa16(uint32_t dst, const void* src) {
    asm volatile("cp.async.cg.shared.global [%0], [%1], 16;" :: "r"(dst), "l"(src) : "memory");
}
#define CP_COMMIT() asm volatile("cp.async.commit_group;" ::: "memory")
#define CP_WAIT(n)  asm volatile("cp.async.wait_group %0;" :: "n"(n) : "memory")

#define LDSM4(r, a)                                                                   \
    asm volatile("ldmatrix.sync.aligned.m8n8.x4.shared.b16 {%0,%1,%2,%3}, [%4];"     \
        : "=r"((r)[0]), "=r"((r)[1]), "=r"((r)[2]), "=r"((r)[3]) : "r"(a))

__device__ __forceinline__ void mma_bf16(float* d, const uint32_t* a, uint32_t b0, uint32_t b1) {
    asm volatile(
        "mma.sync.aligned.m16n8k16.row.col.f32.bf16.bf16.f32 "
        "{%0,%1,%2,%3},{%4,%5,%6,%7},{%8,%9},{%0,%1,%2,%3};"
        : "+f"(d[0]), "+f"(d[1]), "+f"(d[2]), "+f"(d[3])
        : "r"(a[0]), "r"(a[1]), "r"(a[2]), "r"(a[3]), "r"(b0), "r"(b1));
}

// ---------------- prep: coalesced transpose + bf16 split ----------------
__global__ void prep_w1(const float* __restrict__ w1a, const float* __restrict__ w1b) {
    if (blockIdx.x == 0 && blockIdx.y == 0 && blockIdx.z == 0 && threadIdx.x < NLEAF)
        g_count[threadIdx.x] = 0;
    const int leaf = blockIdx.z, kt = blockIdx.y, ft = blockIdx.x;  // kt<16, ft<4
    __shared__ float ta[32][33], tb[32][33];
    const int tid = threadIdx.x;
    {
        int r = tid >> 3, cq = tid & 7;
        size_t src = ((size_t)leaf * 512 + kt * 32 + r) * 128 + ft * 32 + cq * 4;
        float4 va = *(const float4*)(w1a + src);
        float4 vb = *(const float4*)(w1b + src);
        ta[r][cq*4+0]=va.x; ta[r][cq*4+1]=va.y; ta[r][cq*4+2]=va.z; ta[r][cq*4+3]=va.w;
        tb[r][cq*4+0]=vb.x; tb[r][cq*4+1]=vb.y; tb[r][cq*4+2]=vb.z; tb[r][cq*4+3]=vb.w;
    }
    __syncthreads();
    {
        int n = tid >> 2, kq = tid & 3;
        int f = n >> 1, side = n & 1;
        union { __nv_bfloat16 b[8]; uint4 u; } h8, l8;
        #pragma unroll
        for (int j = 0; j < 8; j++) {
            float v = side ? tb[kq * 8 + j][f] : ta[kq * 8 + j][f];
            split_bf16(v, h8.b[j], l8.b[j]);
        }
        size_t orow = ((size_t)leaf * 256 + ft * 64 + n) * 512 + kt * 32 + kq * 8;
        *(uint4*)(g_w1t_hi + orow) = h8.u;
        *(uint4*)(g_w1t_lo + orow) = l8.u;
    }
}

__global__ void prep_w2(const float* __restrict__ w2) {
    const int leaf = blockIdx.z, kt = blockIdx.y, dt = blockIdx.x;  // kt<4, dt<16
    __shared__ float t[32][33];
    const int tid = threadIdx.x;
    {
        int r = tid >> 3, cq = tid & 7;
        size_t src = ((size_t)leaf * 128 + kt * 32 + r) * 512 + dt * 32 + cq * 4;
        float4 v = *(const float4*)(w2 + src);
        t[r][cq*4+0]=v.x; t[r][cq*4+1]=v.y; t[r][cq*4+2]=v.z; t[r][cq*4+3]=v.w;
    }
    __syncthreads();
    {
        int n = tid >> 3, kq = tid & 7;
        union { __nv_bfloat16 b[4]; uint2 u; } h4, l4;
        #pragma unroll
        for (int j = 0; j < 4; j++) split_bf16(t[kq * 4 + j][n], h4.b[j], l4.b[j]);
        size_t orow = ((size_t)leaf * 512 + dt * 32 + n) * 128 + kt * 32 + kq * 4;
        *(uint2*)(g_w2t_hi + orow) = h4.u;
        *(uint2*)(g_w2t_lo + orow) = l4.u;
    }
}

// ---------------- routing + X split ----------------
__device__ __forceinline__ float warp_sum(float v) {
    #pragma unroll
    for (int o = 16; o > 0; o >>= 1) v += __shfl_xor_sync(0xFFFFFFFFu, v, o);
    return v;
}

__global__ void route_kernel(const float* __restrict__ x,
                             const float* __restrict__ wn0, const float* __restrict__ bn0,
                             const float* __restrict__ wn1, const float* __restrict__ bn1,
                             const float* __restrict__ wn2, const float* __restrict__ bn2)
{
    int gwarp = (blockIdx.x * blockDim.x + threadIdx.x) >> 5;
    int lane  = threadIdx.x & 31;
    if (gwarp >= TOKENS) return;

    const float4* xr4 = (const float4*)(x + (size_t)gwarp * DIM);
    float4 xv[4];
    #pragma unroll
    for (int i = 0; i < 4; i++) xv[i] = xr4[lane + i * 32];

    // write split activations (reused by ffn via cp.async)
    {
        __nv_bfloat16* xh = g_x_hi + (size_t)gwarp * DIM;
        __nv_bfloat16* xl = g_x_lo + (size_t)gwarp * DIM;
        #pragma unroll
        for (int i = 0; i < 4; i++) {
            float v[4] = { xv[i].x, xv[i].y, xv[i].z, xv[i].w };
            union { __nv_bfloat16 b[4]; uint2 u; } h4, l4;
            #pragma unroll
            for (int j = 0; j < 4; j++) split_bf16(v[j], h4.b[j], l4.b[j]);
            *(uint2*)(xh + (lane + i * 32) * 4) = h4.u;
            *(uint2*)(xl + (lane + i * 32) * 4) = l4.u;
        }
    }

    float s = 0.f;
    #pragma unroll
    for (int i = 0; i < 4; i++) {
        int base = (lane + i * 32) * 4;
        s += xv[i].x * wn0[base + 0] + xv[i].y * wn0[base + 1]
           + xv[i].z * wn0[base + 2] + xv[i].w * wn0[base + 3];
    }
    s = warp_sum(s) + bn0[0];
    int node = (s > 0.f) ? 0 : 1;

    s = 0.f;
    #pragma unroll
    for (int i = 0; i < 4; i++) {
        int base = (lane + i * 32) * 4;
        s += xv[i].x * wn1[(base + 0) * 2 + node] + xv[i].y * wn1[(base + 1) * 2 + node]
           + xv[i].z * wn1[(base + 2) * 2 + node] + xv[i].w * wn1[(base + 3) * 2 + node];
    }
    s = warp_sum(s) + bn1[node];
    node = node * 2 + ((s > 0.f) ? 0 : 1);

    s = 0.f;
    #pragma unroll
    for (int i = 0; i < 4; i++) {
        int base = (lane + i * 32) * 4;
        s += xv[i].x * wn2[(base + 0) * 4 + node] + xv[i].y * wn2[(base + 1) * 4 + node]
           + xv[i].z * wn2[(base + 2) * 4 + node] + xv[i].w * wn2[(base + 3) * 4 + node];
    }
    s = warp_sum(s) + bn2[node];
    int leaf = node * 2 + ((s > 0.f) ? 0 : 1);

    if (lane == 0) {
        int pos = atomicAdd(&g_count[leaf], 1);
        g_list[leaf * TOKENS + pos] = gwarp;
    }
}

// ---------------- SMEM layout ----------------
#define SM_ROWTOK  0                        // 64*4
#define SM_B1A     256                      // 512B
#define SM_B1B     768
#define SM_B2      1280                     // 2KB
#define SM_X       4096                     // [2 buf][hi 8KB | lo 8KB] = 32KB
#define SM_W       36864                    // [2 buf][hi 32KB | lo 32KB] = 128KB
#define SM_H       167936                   // hi0,hi1,lo0,lo1 each 8KB = 32KB
#define SMEM_TOTAL 200704

#define XHI(p) (sb + SM_X + (p) * 16384)
#define XLO(p) (sb + SM_X + (p) * 16384 + 8192)
#define WHI(p) (sb + SM_W + (p) * 65536)
#define WLO(p) (sb + SM_W + (p) * 65536 + 32768)
#define HHI(k) (sb + SM_H + (k) * 8192)
#define HLO(k) (sb + SM_H + 16384 + (k) * 8192)

// ---------------- fused leaf FFN: cp.async-pipelined bf16-split mma.sync ----------------
__global__ void __launch_bounds__(256, 1)
ffn_kernel(const float* __restrict__ b1a, const float* __restrict__ b1b,
           const float* __restrict__ b2,  float* __restrict__ out)
{
    extern __shared__ char smem[];
    const uint32_t sb = smem_u32(smem);
    const int tid  = threadIdx.x;
    const int wid  = tid >> 5;
    const int lane = tid & 31;

    const int leaf  = blockIdx.x;
    const int cnt   = g_count[leaf];
    const int start = blockIdx.y * BM;
    if (start >= cnt) return;
    const int rows = min(BM, cnt - start);
    const int* list = g_list + leaf * TOKENS + start;

    int* rowTok = (int*)(smem + SM_ROWTOK);
    if (tid < BM) rowTok[tid] = list[min(tid, rows - 1)];
    {
        float* sB1a = (float*)(smem + SM_B1A);
        float* sB1b = (float*)(smem + SM_B1B);
        float* sB2  = (float*)(smem + SM_B2);
        if (tid < FDIM) { sB1a[tid] = b1a[leaf * FDIM + tid]; sB1b[tid] = b1b[leaf * FDIM + tid]; }
        for (int i = tid; i < DIM; i += 256) sB2[i] = b2[leaf * DIM + i];
    }
    __syncthreads();

    const int wm = wid & 1;        // m-block: rows 32*wm..+31
    const int wn = wid >> 1;       // n-block: cols 64*wn..+63
    const int gid = lane >> 2, tig = lane & 3;
    const int a_row = lane & 15;
    const int a_kad = (lane & 16) >> 1;
    const int b_row = (lane & 7) | ((lane >> 1) & 8);
    const int b_kad = lane & 8;

    // ---- chunk loader: c 0..7 = GEMM1 (X + W1), c 8..11 = GEMM2 (W2) ----
    const int xrow = tid >> 2, xq = (tid & 3) * 2;       // X: 2x16B (+lo) per thread
    auto issue = [&](int c) {
        const int p = c & 1;
        if (c < 8) {
            const int k0 = c * 64;
            const __nv_bfloat16* xh = g_x_hi + (size_t)rowTok[xrow] * DIM + k0;
            const __nv_bfloat16* xl = g_x_lo + (size_t)rowTok[xrow] * DIM + k0;
            #pragma unroll
            for (int j = 0; j < 2; j++) {
                uint32_t so = sw128((uint32_t)(xrow * 128 + (xq + j) * 16));
                cpa16(XHI(p) + so, xh + (xq + j) * 8);
                cpa16(XLO(p) + so, xl + (xq + j) * 8);
            }
            const __nv_bfloat16* wh = g_w1t_hi + ((size_t)(leaf * 256 + tid)) * DIM + k0;
            const __nv_bfloat16* wl = g_w1t_lo + ((size_t)(leaf * 256 + tid)) * DIM + k0;
            #pragma unroll
            for (int q = 0; q < 8; q++) {
                uint32_t so = sw128((uint32_t)(tid * 128 + q * 16));
                cpa16(WHI(p) + so, wh + q * 8);
                cpa16(WLO(p) + so, wl + q * 8);
            }
        } else {
            const int idx = c - 8, nh = idx >> 1, c2 = idx & 1;
            const __nv_bfloat16* wh = g_w2t_hi + ((size_t)(leaf * 512 + nh * 256 + tid)) * FDIM + c2 * 64;
            const __nv_bfloat16* wl = g_w2t_lo + ((size_t)(leaf * 512 + nh * 256 + tid)) * FDIM + c2 * 64;
            #pragma unroll
            for (int q = 0; q < 8; q++) {
                uint32_t so = sw128((uint32_t)(tid * 128 + q * 16));
                cpa16(WHI(p) + so, wh + q * 8);
                cpa16(WLO(p) + so, wl + q * 8);
            }
        }
        CP_COMMIT();
    };

    float acc[2][8][4];
    float acc2[2][8][4];
    #pragma unroll
    for (int s = 0; s < 2; s++)
        #pragma unroll
        for (int t = 0; t < 8; t++)
            #pragma unroll
            for (int j = 0; j < 4; j++) { acc[s][t][j] = 0.f; acc2[s][t][j] = 0.f; }

    issue(0);

    for (int c = 0; c < 12; c++) {
        const int p = c & 1;
        if (c < 11) issue(c + 1);
        if (c < 11) { CP_WAIT(1); } else { CP_WAIT(0); }
        __syncthreads();

        if (c == 8) {
            // epilogue1: gate adjacent (a,b) cols -> H bf16 hi/lo (runs once, after GEMM1)
            const float* sB1a = (const float*)(smem + SM_B1A);
            const float* sB1b = (const float*)(smem + SM_B1B);
            #pragma unroll
            for (int s = 0; s < 2; s++) {
                const int r0 = 32 * wm + 16 * s + gid;
                #pragma unroll
                for (int t = 0; t < 8; t++) {
                    const int f = 32 * wn + 4 * t + tig;
                    const float ba = sB1a[f], bb = sB1b[f];
                    const float h0 = (acc[s][t][0] + ba) * (acc[s][t][1] + bb);
                    const float h1 = (acc[s][t][2] + ba) * (acc[s][t][3] + bb);
                    const int kc = f >> 6, fk = f & 63;
                    const uint32_t o0 = sw128((uint32_t)(r0 * 128 + fk * 2));
                    const uint32_t o1 = sw128((uint32_t)((r0 + 8) * 128 + fk * 2));
                    __nv_bfloat16 hh0, hl0, hh1, hl1;
                    split_bf16(h0, hh0, hl0);
                    split_bf16(h1, hh1, hl1);
                    *(__nv_bfloat16*)(HHI(kc) + o0 - sb + smem) = hh0;
                    *(__nv_bfloat16*)(HLO(kc) + o0 - sb + smem) = hl0;
                    *(__nv_bfloat16*)(HHI(kc) + o1 - sb + smem) = hh1;
                    *(__nv_bfloat16*)(HLO(kc) + o1 - sb + smem) = hl1;
                }
            }
            __syncthreads();
        }

        if (c < 8) {
            // GEMM1 mma on buffer p
            #pragma unroll
            for (int pass = 0; pass < 3; pass++) {
                const uint32_t abase = (pass == 2) ? XLO(p) : XHI(p);
                const uint32_t bbase = (pass == 1) ? WLO(p) : WHI(p);
                #pragma unroll
                for (int kof = 0; kof < 64; kof += 16) {
                    uint32_t afr[2][4];
                    #pragma unroll
                    for (int s = 0; s < 2; s++)
                        LDSM4(afr[s], abase + sw128((uint32_t)((32 * wm + 16 * s + a_row) * 128
                                                               + (kof + a_kad) * 2)));
                    #pragma unroll
                    for (int nt = 0; nt < 4; nt++) {
                        uint32_t bfr[4];
                        LDSM4(bfr, bbase + sw128((uint32_t)((64 * wn + 16 * nt + b_row) * 128
                                                            + (kof + b_kad) * 2)));
                        #pragma unroll
                        for (int s = 0; s < 2; s++) {
                            mma_bf16(acc[s][2 * nt],     afr[s], bfr[0], bfr[1]);
                            mma_bf16(acc[s][2 * nt + 1], afr[s], bfr[2], bfr[3]);
                        }
                    }
                }
            }
        } else {
            const int idx = c - 8, nh = idx >> 1, c2 = idx & 1;
            // GEMM2 mma: A = H chunk c2, B = W2 buffer p
            #pragma unroll
            for (int pass = 0; pass < 3; pass++) {
                const uint32_t abase = (pass == 2) ? HLO(c2) : HHI(c2);
                const uint32_t bbase = (pass == 1) ? WLO(p) : WHI(p);
                #pragma unroll
                for (int kof = 0; kof < 64; kof += 16) {
                    uint32_t afr[2][4];
                    #pragma unroll
                    for (int s = 0; s < 2; s++)
                        LDSM4(afr[s], abase + sw128((uint32_t)((32 * wm + 16 * s + a_row) * 128
                                                               + (kof + a_kad) * 2)));
                    #pragma unroll
                    for (int nt = 0; nt < 4; nt++) {
                        uint32_t bfr[4];
                        LDSM4(bfr, bbase + sw128((uint32_t)((64 * wn + 16 * nt + b_row) * 128
                                                            + (kof + b_kad) * 2)));
                        #pragma unroll
                        for (int s = 0; s < 2; s++) {
                            mma_bf16(acc2[s][2 * nt],     afr[s], bfr[0], bfr[1]);
                            mma_bf16(acc2[s][2 * nt + 1], afr[s], bfr[2], bfr[3]);
                        }
                    }
                }
            }
            if (c2 == 1) {
                // epilogue2: bias + direct stores, then reset acc2 for next half
                const float* sB2 = (const float*)(smem + SM_B2);
                #pragma unroll
                for (int s = 0; s < 2; s++) {
                    const int r0 = 32 * wm + 16 * s + gid;
                    #pragma unroll
                    for (int t = 0; t < 8; t++) {
                        const int col = nh * 256 + 64 * wn + 8 * t + 2 * tig;
                        const float c0 = sB2[col], c1 = sB2[col + 1];
                        if (r0 < rows) {
                            float2 v = { acc2[0 + s - s][t][0], 0.f }; // placeholder avoided below
                        }
                        // (explicit stores)
                        if (r0 < rows) {
                            float2 v = { acc2[s][t][0] + c0, acc2[s][t][1] + c1 };
                            *(float2*)(out + (size_t)rowTok[r0] * DIM + col) = v;
                        }
                        if (r0 + 8 < rows) {
                            float2 v = { acc2[s][t][2] + c0, acc2[s][t][3] + c1 };
                            *(float2*)(out + (size_t)rowTok[r0 + 8] * DIM + col) = v;
                        }
                        #pragma unroll
                        for (int j = 0; j < 4; j++) acc2[s][t][j] = 0.f;
                    }
                }
            }
        }
        __syncthreads();
    }
}

extern "C" void kernel_launch(void* const* d_in, const int* in_sizes, int n_in,
                              void* d_out, int out_size)
{
    const float* x   = (const float*)d_in[0];
    const float* wn0 = (const float*)d_in[2];
    const float* bn0 = (const float*)d_in[3];
    const float* wn1 = (const float*)d_in[4];
    const float* bn1 = (const float*)d_in[5];
    const float* wn2 = (const float*)d_in[6];
    const float* bn2 = (const float*)d_in[7];
    const float* w1a = (const float*)d_in[8];
    const float* b1a = (const float*)d_in[9];
    const float* w1b = (const float*)d_in[10];
    const float* b1b = (const float*)d_in[11];
    const float* w2  = (const float*)d_in[12];
    const float* b2  = (const float*)d_in[13];
    float* out = (float*)d_out;

    static_assert(SMEM_TOTAL <= 227 * 1024, "smem");
    cudaFuncSetAttribute(ffn_kernel, cudaFuncAttributeMaxDynamicSharedMemorySize, SMEM_TOTAL);

    prep_w1<<<dim3(4, 16, NLEAF), 256>>>(w1a, w1b);     // also zeroes g_count
    prep_w2<<<dim3(16, 4, NLEAF), 256>>>(w2);
    route_kernel<<<(TOKENS * 32) / 256, 256>>>(x, wn0, bn0, wn1, bn1, wn2, bn2);
    dim3 grid(NLEAF, MAXTILES);
    ffn_kernel<<<grid, 256, SMEM_TOTAL>>>(b1a, b1b, b2, out);
}

// round 6
// speedup vs baseline: 1.9643x; 1.2412x over previous
#include <cuda_runtime.h>
#include <cuda_bf16.h>
#include <cstdint>

#define TOKENS   8192
#define DIM      512
#define FDIM     128
#define NLEAF    8
#define BM       64
#define MAXTILES 32
#define THREADS  512

// ---------------- scratch ----------------
__device__ int g_count[NLEAF];
__device__ int g_list[NLEAF * TOKENS];
__device__ __nv_bfloat16 g_x_hi[TOKENS * DIM];
__device__ __nv_bfloat16 g_x_lo[TOKENS * DIM];
// W1 transposed+interleaved+split: [leaf][n=256][k=512]; n=2f -> w1a col f, n=2f+1 -> w1b col f
__device__ __nv_bfloat16 g_w1t_hi[NLEAF * 256 * 512];
__device__ __nv_bfloat16 g_w1t_lo[NLEAF * 256 * 512];
// W2 transposed+split: [leaf][n=512][k=128]
__device__ __nv_bfloat16 g_w2t_hi[NLEAF * 512 * 128];
__device__ __nv_bfloat16 g_w2t_lo[NLEAF * 512 * 128];

__device__ __forceinline__ uint32_t smem_u32(const void* p) {
    uint32_t a;
    asm("{ .reg .u64 t; cvta.to.shared.u64 t, %1; cvt.u32.u64 %0, t; }" : "=r"(a) : "l"(p));
    return a;
}
__device__ __forceinline__ uint32_t sw128(uint32_t off) { return off ^ ((off >> 3) & 0x70); }

__device__ __forceinline__ void split_bf16(float v, __nv_bfloat16& h, __nv_bfloat16& l) {
    h = __float2bfloat16(v);
    l = __float2bfloat16(v - __bfloat162float(h));
}

__device__ __forceinline__ void cpa16(uint32_t dst, const void* src) {
    asm volatile("cp.async.cg.shared.global [%0], [%1], 16;" :: "r"(dst), "l"(src) : "memory");
}
#define CP_COMMIT() asm volatile("cp.async.commit_group;" ::: "memory")
#define CP_WAIT(n)  asm volatile("cp.async.wait_group %0;" :: "n"(n) : "memory")

#define LDSM4(r, a)                                                                   \
    asm volatile("ldmatrix.sync.aligned.m8n8.x4.shared.b16 {%0,%1,%2,%3}, [%4];"     \
        : "=r"((r)[0]), "=r"((r)[1]), "=r"((r)[2]), "=r"((r)[3]) : "r"(a))

__device__ __forceinline__ void mma_bf16(float* d, const uint32_t* a, uint32_t b0, uint32_t b1) {
    asm volatile(
        "mma.sync.aligned.m16n8k16.row.col.f32.bf16.bf16.f32 "
        "{%0,%1,%2,%3},{%4,%5,%6,%7},{%8,%9},{%0,%1,%2,%3};"
        : "+f"(d[0]), "+f"(d[1]), "+f"(d[2]), "+f"(d[3])
        : "r"(a[0]), "r"(a[1]), "r"(a[2]), "r"(a[3]), "r"(b0), "r"(b1));
}

// ---------------- prep (fused): zero counters + transpose/split W1 & W2 ----------------
__global__ void prep_kernel(const float* __restrict__ w1a, const float* __restrict__ w1b,
                            const float* __restrict__ w2) {
    const int bid = blockIdx.x;
    const int tid = threadIdx.x;
    if (bid == 0 && tid < NLEAF) g_count[tid] = 0;

    if (bid < 512) {    // ---- W1: leaf/kt/ft ----
        const int leaf = bid >> 6, rem = bid & 63, kt = rem >> 2, ft = rem & 3;
        __shared__ float ta[32][33], tb[32][33];
        {
            int r = tid >> 3, cq = tid & 7;
            size_t src = ((size_t)leaf * 512 + kt * 32 + r) * 128 + ft * 32 + cq * 4;
            float4 va = *(const float4*)(w1a + src);
            float4 vb = *(const float4*)(w1b + src);
            ta[r][cq*4+0]=va.x; ta[r][cq*4+1]=va.y; ta[r][cq*4+2]=va.z; ta[r][cq*4+3]=va.w;
            tb[r][cq*4+0]=vb.x; tb[r][cq*4+1]=vb.y; tb[r][cq*4+2]=vb.z; tb[r][cq*4+3]=vb.w;
        }
        __syncthreads();
        {
            int n = tid >> 2, kq = tid & 3;
            int f = n >> 1, side = n & 1;
            union { __nv_bfloat16 b[8]; uint4 u; } h8, l8;
            #pragma unroll
            for (int j = 0; j < 8; j++) {
                float v = side ? tb[kq * 8 + j][f] : ta[kq * 8 + j][f];
                split_bf16(v, h8.b[j], l8.b[j]);
            }
            size_t orow = ((size_t)leaf * 256 + ft * 64 + n) * 512 + kt * 32 + kq * 8;
            *(uint4*)(g_w1t_hi + orow) = h8.u;
            *(uint4*)(g_w1t_lo + orow) = l8.u;
        }
    } else {            // ---- W2: leaf/kt/dt ----
        const int b2i = bid - 512;
        const int leaf = b2i >> 6, rem = b2i & 63, dt = rem >> 2, kt = rem & 3;
        __shared__ float t[32][33];
        {
            int r = tid >> 3, cq = tid & 7;
            size_t src = ((size_t)leaf * 128 + kt * 32 + r) * 512 + dt * 32 + cq * 4;
            float4 v = *(const float4*)(w2 + src);
            t[r][cq*4+0]=v.x; t[r][cq*4+1]=v.y; t[r][cq*4+2]=v.z; t[r][cq*4+3]=v.w;
        }
        __syncthreads();
        {
            int n = tid >> 3, kq = tid & 7;
            union { __nv_bfloat16 b[4]; uint2 u; } h4, l4;
            #pragma unroll
            for (int j = 0; j < 4; j++) split_bf16(t[kq * 4 + j][n], h4.b[j], l4.b[j]);
            size_t orow = ((size_t)leaf * 512 + dt * 32 + n) * 128 + kt * 32 + kq * 4;
            *(uint2*)(g_w2t_hi + orow) = h4.u;
            *(uint2*)(g_w2t_lo + orow) = l4.u;
        }
    }
}

// ---------------- routing + X split ----------------
__device__ __forceinline__ float warp_sum(float v) {
    #pragma unroll
    for (int o = 16; o > 0; o >>= 1) v += __shfl_xor_sync(0xFFFFFFFFu, v, o);
    return v;
}

__global__ void route_kernel(const float* __restrict__ x,
                             const float* __restrict__ wn0, const float* __restrict__ bn0,
                             const float* __restrict__ wn1, const float* __restrict__ bn1,
                             const float* __restrict__ wn2, const float* __restrict__ bn2)
{
    int gwarp = (blockIdx.x * blockDim.x + threadIdx.x) >> 5;
    int lane  = threadIdx.x & 31;
    if (gwarp >= TOKENS) return;

    const float4* xr4 = (const float4*)(x + (size_t)gwarp * DIM);
    float4 xv[4];
    #pragma unroll
    for (int i = 0; i < 4; i++) xv[i] = xr4[lane + i * 32];

    {
        __nv_bfloat16* xh = g_x_hi + (size_t)gwarp * DIM;
        __nv_bfloat16* xl = g_x_lo + (size_t)gwarp * DIM;
        #pragma unroll
        for (int i = 0; i < 4; i++) {
            float v[4] = { xv[i].x, xv[i].y, xv[i].z, xv[i].w };
            union { __nv_bfloat16 b[4]; uint2 u; } h4, l4;
            #pragma unroll
            for (int j = 0; j < 4; j++) split_bf16(v[j], h4.b[j], l4.b[j]);
            *(uint2*)(xh + (lane + i * 32) * 4) = h4.u;
            *(uint2*)(xl + (lane + i * 32) * 4) = l4.u;
        }
    }

    float s = 0.f;
    #pragma unroll
    for (int i = 0; i < 4; i++) {
        int base = (lane + i * 32) * 4;
        s += xv[i].x * wn0[base + 0] + xv[i].y * wn0[base + 1]
           + xv[i].z * wn0[base + 2] + xv[i].w * wn0[base + 3];
    }
    s = warp_sum(s) + bn0[0];
    int node = (s > 0.f) ? 0 : 1;

    s = 0.f;
    #pragma unroll
    for (int i = 0; i < 4; i++) {
        int base = (lane + i * 32) * 4;
        s += xv[i].x * wn1[(base + 0) * 2 + node] + xv[i].y * wn1[(base + 1) * 2 + node]
           + xv[i].z * wn1[(base + 2) * 2 + node] + xv[i].w * wn1[(base + 3) * 2 + node];
    }
    s = warp_sum(s) + bn1[node];
    node = node * 2 + ((s > 0.f) ? 0 : 1);

    s = 0.f;
    #pragma unroll
    for (int i = 0; i < 4; i++) {
        int base = (lane + i * 32) * 4;
        s += xv[i].x * wn2[(base + 0) * 4 + node] + xv[i].y * wn2[(base + 1) * 4 + node]
           + xv[i].z * wn2[(base + 2) * 4 + node] + xv[i].w * wn2[(base + 3) * 4 + node];
    }
    s = warp_sum(s) + bn2[node];
    int leaf = node * 2 + ((s > 0.f) ? 0 : 1);

    if (lane == 0) {
        int pos = atomicAdd(&g_count[leaf], 1);
        g_list[leaf * TOKENS + pos] = gwarp;
    }
}

// ---------------- SMEM layout ----------------
#define SM_ROWTOK  0                        // 256B
#define SM_B1A     256
#define SM_B1B     768
#define SM_B2      1280                     // 2KB
#define SM_X       4096                     // 2 buf x (hi 8KB | lo 8KB) = 32KB
#define SM_W       36864                    // 2 buf x (hi 32KB | lo 32KB) = 128KB
#define SM_H       167936                   // hi0,hi1 (16KB) then lo0,lo1 (16KB)
#define SMEM_TOTAL 200704

#define XHI(p) (sb + SM_X + (p) * 16384)
#define XLO(p) (sb + SM_X + (p) * 16384 + 8192)
#define WHI(p) (sb + SM_W + (p) * 65536)
#define WLO(p) (sb + SM_W + (p) * 65536 + 32768)
#define HHI(k) (sb + SM_H + (k) * 8192)
#define HLO(k) (sb + SM_H + 16384 + (k) * 8192)

// ---------------- fused leaf FFN: 16 warps, scoped accumulators ----------------
__global__ void __launch_bounds__(THREADS, 1)
ffn_kernel(const float* __restrict__ b1a, const float* __restrict__ b1b,
           const float* __restrict__ b2,  float* __restrict__ out)
{
    extern __shared__ char smem[];
    const uint32_t sb = smem_u32(smem);
    const int tid  = threadIdx.x;
    const int wid  = tid >> 5;
    const int lane = tid & 31;

    const int leaf  = blockIdx.x;
    const int cnt   = g_count[leaf];
    const int start = blockIdx.y * BM;
    if (start >= cnt) return;
    const int rows = min(BM, cnt - start);
    const int* list = g_list + leaf * TOKENS + start;

    int* rowTok = (int*)(smem + SM_ROWTOK);
    if (tid < BM) rowTok[tid] = list[min(tid, rows - 1)];
    {
        float* sB1a = (float*)(smem + SM_B1A);
        float* sB1b = (float*)(smem + SM_B1B);
        float* sB2  = (float*)(smem + SM_B2);
        if (tid < FDIM) { sB1a[tid] = b1a[leaf * FDIM + tid]; sB1b[tid] = b1b[leaf * FDIM + tid]; }
        if (tid < DIM)  sB2[tid] = b2[leaf * DIM + tid];
    }
    __syncthreads();

    const int wm = wid & 3;        // m-block: rows 16*wm..+15
    const int wn = wid >> 2;       // n-block: cols 64*wn..+63
    const int gid = lane >> 2, tig = lane & 3;
    const int a_row = lane & 15;
    const int a_kad = (lane & 16) >> 1;
    const int b_row = (lane & 7) | ((lane >> 1) & 8);
    const int b_kad = lane & 8;

    // ---- chunk loader: c 0..7 = GEMM1 (X + W1), c 8..11 = GEMM2 (W2) ----
    const int xrow = tid >> 3, xq = tid & 7;     // X: one 16B (hi + lo) per thread
    auto issue = [&](int c) {
        const int p = c & 1;
        if (c < 8) {
            const int k0 = c * 64;
            const __nv_bfloat16* xh = g_x_hi + (size_t)rowTok[xrow] * DIM + k0;
            const __nv_bfloat16* xl = g_x_lo + (size_t)rowTok[xrow] * DIM + k0;
            uint32_t so = sw128((uint32_t)(xrow * 128 + xq * 16));
            cpa16(XHI(p) + so, xh + xq * 8);
            cpa16(XLO(p) + so, xl + xq * 8);
            const __nv_bfloat16* whb = g_w1t_hi + (size_t)leaf * 256 * DIM + k0;
            const __nv_bfloat16* wlb = g_w1t_lo + (size_t)leaf * 256 * DIM + k0;
            #pragma unroll
            for (int it = 0; it < 4; it++) {
                int idx = tid + it * THREADS;
                int wrow = idx >> 3, q = idx & 7;
                uint32_t wo = sw128((uint32_t)(wrow * 128 + q * 16));
                cpa16(WHI(p) + wo, whb + (size_t)wrow * DIM + q * 8);
                cpa16(WLO(p) + wo, wlb + (size_t)wrow * DIM + q * 8);
            }
        } else {
            const int idx4 = c - 8, nh = idx4 >> 1, c2 = idx4 & 1;
            const __nv_bfloat16* whb = g_w2t_hi + ((size_t)(leaf * 512 + nh * 256)) * FDIM + c2 * 64;
            const __nv_bfloat16* wlb = g_w2t_lo + ((size_t)(leaf * 512 + nh * 256)) * FDIM + c2 * 64;
            #pragma unroll
            for (int it = 0; it < 4; it++) {
                int idx = tid + it * THREADS;
                int wrow = idx >> 3, q = idx & 7;
                uint32_t wo = sw128((uint32_t)(wrow * 128 + q * 16));
                cpa16(WHI(p) + wo, whb + (size_t)wrow * FDIM + q * 8);
                cpa16(WLO(p) + wo, wlb + (size_t)wrow * FDIM + q * 8);
            }
        }
        CP_COMMIT();
    };

    issue(0);

    // ================= phase 1: GEMM1 (chunks 0..7) =================
    {
        float acc[8][4];
        #pragma unroll
        for (int t = 0; t < 8; t++)
            #pragma unroll
            for (int j = 0; j < 4; j++) acc[t][j] = 0.f;

        for (int c = 0; c < 8; c++) {
            const int p = c & 1;
            issue(c + 1);
            CP_WAIT(1);
            __syncthreads();
            #pragma unroll
            for (int pass = 0; pass < 3; pass++) {
                const uint32_t abase = (pass == 2) ? XLO(p) : XHI(p);
                const uint32_t bbase = (pass == 1) ? WLO(p) : WHI(p);
                #pragma unroll
                for (int kof = 0; kof < 64; kof += 16) {
                    uint32_t afr[4];
                    LDSM4(afr, abase + sw128((uint32_t)((16 * wm + a_row) * 128
                                                        + (kof + a_kad) * 2)));
                    #pragma unroll
                    for (int nt = 0; nt < 4; nt++) {
                        uint32_t bfr[4];
                        LDSM4(bfr, bbase + sw128((uint32_t)((64 * wn + 16 * nt + b_row) * 128
                                                            + (kof + b_kad) * 2)));
                        mma_bf16(acc[2 * nt],     afr, bfr[0], bfr[1]);
                        mma_bf16(acc[2 * nt + 1], afr, bfr[2], bfr[3]);
                    }
                }
            }
            __syncthreads();
        }

        // epilogue1: gate interleaved (a,b) col pairs -> H bf16 hi/lo
        const float* sB1a = (const float*)(smem + SM_B1A);
        const float* sB1b = (const float*)(smem + SM_B1B);
        const int r0 = 16 * wm + gid;
        #pragma unroll
        for (int t = 0; t < 8; t++) {
            const int f = 32 * wn + 4 * t + tig;
            const float ba = sB1a[f], bb = sB1b[f];
            const float h0 = (acc[t][0] + ba) * (acc[t][1] + bb);
            const float h1 = (acc[t][2] + ba) * (acc[t][3] + bb);
            const int kc = f >> 6, fk = f & 63;
            const uint32_t o0 = sw128((uint32_t)(r0 * 128 + fk * 2));
            const uint32_t o1 = sw128((uint32_t)((r0 + 8) * 128 + fk * 2));
            char* hh = smem + (HHI(kc) - sb);
            char* hl = smem + (HLO(kc) - sb);
            __nv_bfloat16 hh0, hl0, hh1, hl1;
            split_bf16(h0, hh0, hl0);
            split_bf16(h1, hh1, hl1);
            *(__nv_bfloat16*)(hh + o0) = hh0;  *(__nv_bfloat16*)(hl + o0) = hl0;
            *(__nv_bfloat16*)(hh + o1) = hh1;  *(__nv_bfloat16*)(hl + o1) = hl1;
        }
    }

    // ================= phase 2: GEMM2 (chunks 8..11) =================
    {
        const float* sB2 = (const float*)(smem + SM_B2);
        int c = 8;
        for (int nh = 0; nh < 2; nh++) {
            float acc2[8][4];
            #pragma unroll
            for (int t = 0; t < 8; t++)
                #pragma unroll
                for (int j = 0; j < 4; j++) acc2[t][j] = 0.f;

            #pragma unroll
            for (int c2 = 0; c2 < 2; c2++, c++) {
                const int p = c & 1;
                if (c < 11) { issue(c + 1); CP_WAIT(1); } else { CP_WAIT(0); }
                __syncthreads();   // also orders epilogue1's H writes before first H read
                #pragma unroll
                for (int pass = 0; pass < 3; pass++) {
                    const uint32_t abase = (pass == 2) ? HLO(c2) : HHI(c2);
                    const uint32_t bbase = (pass == 1) ? WLO(p) : WHI(p);
                    #pragma unroll
                    for (int kof = 0; kof < 64; kof += 16) {
                        uint32_t afr[4];
                        LDSM4(afr, abase + sw128((uint32_t)((16 * wm + a_row) * 128
                                                            + (kof + a_kad) * 2)));
                        #pragma unroll
                        for (int nt = 0; nt < 4; nt++) {
                            uint32_t bfr[4];
                            LDSM4(bfr, bbase + sw128((uint32_t)((64 * wn + 16 * nt + b_row) * 128
                                                                + (kof + b_kad) * 2)));
                            mma_bf16(acc2[2 * nt],     afr, bfr[0], bfr[1]);
                            mma_bf16(acc2[2 * nt + 1], afr, bfr[2], bfr[3]);
                        }
                    }
                }
                __syncthreads();
            }

            // epilogue2: bias + direct stores
            const int r0 = 16 * wm + gid;
            #pragma unroll
            for (int t = 0; t < 8; t++) {
                const int col = nh * 256 + 64 * wn + 8 * t + 2 * tig;
                const float c0 = sB2[col], c1 = sB2[col + 1];
                if (r0 < rows) {
                    float2 v = { acc2[t][0] + c0, acc2[t][1] + c1 };
                    *(float2*)(out + (size_t)rowTok[r0] * DIM + col) = v;
                }
                if (r0 + 8 < rows) {
                    float2 v = { acc2[t][2] + c0, acc2[t][3] + c1 };
                    *(float2*)(out + (size_t)rowTok[r0 + 8] * DIM + col) = v;
                }
            }
        }
    }
}

extern "C" void kernel_launch(void* const* d_in, const int* in_sizes, int n_in,
                              void* d_out, int out_size)
{
    const float* x   = (const float*)d_in[0];
    const float* wn0 = (const float*)d_in[2];
    const float* bn0 = (const float*)d_in[3];
    const float* wn1 = (const float*)d_in[4];
    const float* bn1 = (const float*)d_in[5];
    const float* wn2 = (const float*)d_in[6];
    const float* bn2 = (const float*)d_in[7];
    const float* w1a = (const float*)d_in[8];
    const float* b1a = (const float*)d_in[9];
    const float* w1b = (const float*)d_in[10];
    const float* b1b = (const float*)d_in[11];
    const float* w2  = (const float*)d_in[12];
    const float* b2  = (const float*)d_in[13];
    float* out = (float*)d_out;

    static_assert(SMEM_TOTAL <= 227 * 1024, "smem");
    cudaFuncSetAttribute(ffn_kernel, cudaFuncAttributeMaxDynamicSharedMemorySize, SMEM_TOTAL);

    prep_kernel<<<1024, 256>>>(w1a, w1b, w2);            // also zeroes g_count
    route_kernel<<<(TOKENS * 32) / 256, 256>>>(x, wn0, bn0, wn1, bn1, wn2, bn2);
    dim3 grid(NLEAF, MAXTILES);
    ffn_kernel<<<grid, THREADS, SMEM_TOTAL>>>(b1a, b1b, b2, out);
}

// round 7
// speedup vs baseline: 1.9670x; 1.0014x over previous
#include <cuda_runtime.h>
#include <cuda_bf16.h>
#include <cstdint>

#define TOKENS   8192
#define DIM      512
#define FDIM     128
#define NLEAF    8
#define BM       64
#define MAXTILES 32
#define THREADS  512

// ---------------- scratch ----------------
__device__ int g_count[NLEAF];
__device__ int g_list[NLEAF * TOKENS];
__device__ __nv_bfloat16 g_x_hi[TOKENS * DIM];
__device__ __nv_bfloat16 g_x_lo[TOKENS * DIM];
// W1 transposed+split: [leaf][n=256][k=512]; n<128 -> w1a col n, n>=128 -> w1b col n-128
__device__ __nv_bfloat16 g_w1t_hi[NLEAF * 256 * 512];
__device__ __nv_bfloat16 g_w1t_lo[NLEAF * 256 * 512];
// W2 transposed+split: [leaf][n=512][k=128]
__device__ __nv_bfloat16 g_w2t_hi[NLEAF * 512 * 128];
__device__ __nv_bfloat16 g_w2t_lo[NLEAF * 512 * 128];

__device__ __forceinline__ uint32_t smem_u32(const void* p) {
    uint32_t a;
    asm("{ .reg .u64 t; cvta.to.shared.u64 t, %1; cvt.u32.u64 %0, t; }" : "=r"(a) : "l"(p));
    return a;
}
__device__ __forceinline__ uint32_t sw128(uint32_t off) { return off ^ ((off >> 3) & 0x70); }

__device__ __forceinline__ void split_bf16(float v, __nv_bfloat16& h, __nv_bfloat16& l) {
    h = __float2bfloat16(v);
    l = __float2bfloat16(v - __bfloat162float(h));
}
__device__ __forceinline__ uint32_t pack_bf16x2(__nv_bfloat16 a, __nv_bfloat16 b) {
    union { __nv_bfloat16 h[2]; uint32_t u; } t;
    t.h[0] = a; t.h[1] = b;
    return t.u;
}

__device__ __forceinline__ void cpa16(uint32_t dst, const void* src) {
    asm volatile("cp.async.cg.shared.global [%0], [%1], 16;" :: "r"(dst), "l"(src) : "memory");
}
#define CP_COMMIT() asm volatile("cp.async.commit_group;" ::: "memory")
#define CP_WAIT(n)  asm volatile("cp.async.wait_group %0;" :: "n"(n) : "memory")

#define LDSM4(r, a)                                                                   \
    asm volatile("ldmatrix.sync.aligned.m8n8.x4.shared.b16 {%0,%1,%2,%3}, [%4];"     \
        : "=r"((r)[0]), "=r"((r)[1]), "=r"((r)[2]), "=r"((r)[3]) : "r"(a))

__device__ __forceinline__ void mma_bf16(float* d, const uint32_t* a, uint32_t b0, uint32_t b1) {
    asm volatile(
        "mma.sync.aligned.m16n8k16.row.col.f32.bf16.bf16.f32 "
        "{%0,%1,%2,%3},{%4,%5,%6,%7},{%8,%9},{%0,%1,%2,%3};"
        : "+f"(d[0]), "+f"(d[1]), "+f"(d[2]), "+f"(d[3])
        : "r"(a[0]), "r"(a[1]), "r"(a[2]), "r"(a[3]), "r"(b0), "r"(b1));
}

// register-pipelined triple-pass chunk: 12 fragment sets (3 passes x 4 kof),
// prefetch set it+1 while issuing MMAs for set it.
__device__ __forceinline__ void run_chunk(
    float acc[8][4], uint32_t AH, uint32_t AL, uint32_t BH, uint32_t BL,
    uint32_t arow_off, const int br[4], int a_kad, int b_kad)
{
    uint32_t ab[3] = { AH, AH, AL };
    uint32_t bb[3] = { BH, BL, BH };
    uint32_t afr[2][4], bfr[2][4][4];
    LDSM4(afr[0], ab[0] + sw128(arow_off + a_kad * 2));
    #pragma unroll
    for (int nt = 0; nt < 4; nt++)
        LDSM4(bfr[0][nt], bb[0] + sw128((uint32_t)(br[nt] * 128 + b_kad * 2)));
    #pragma unroll
    for (int it = 0; it < 12; it++) {
        const int cur = it & 1, nxt = cur ^ 1;
        if (it < 11) {
            const int jt = it + 1, pass = jt >> 2, kof = (jt & 3) * 16;
            LDSM4(afr[nxt], ab[pass] + sw128(arow_off + (kof + a_kad) * 2));
            #pragma unroll
            for (int nt = 0; nt < 4; nt++)
                LDSM4(bfr[nxt][nt], bb[pass] + sw128((uint32_t)(br[nt] * 128 + (kof + b_kad) * 2)));
        }
        #pragma unroll
        for (int nt = 0; nt < 4; nt++) {
            mma_bf16(acc[2 * nt],     afr[cur], bfr[cur][nt][0], bfr[cur][nt][1]);
            mma_bf16(acc[2 * nt + 1], afr[cur], bfr[cur][nt][2], bfr[cur][nt][3]);
        }
    }
}

// ---------------- prep (fused): zero counters + transpose/split W1 & W2 ----------------
__global__ void prep_kernel(const float* __restrict__ w1a, const float* __restrict__ w1b,
                            const float* __restrict__ w2) {
    const int bid = blockIdx.x;
    const int tid = threadIdx.x;
    if (bid == 0 && tid < NLEAF) g_count[tid] = 0;

    if (bid < 512) {    // ---- W1: leaf/kt/ft ----
        const int leaf = bid >> 6, rem = bid & 63, kt = rem >> 2, ft = rem & 3;
        __shared__ float ta[32][33], tb[32][33];
        {
            int r = tid >> 3, cq = tid & 7;
            size_t src = ((size_t)leaf * 512 + kt * 32 + r) * 128 + ft * 32 + cq * 4;
            float4 va = *(const float4*)(w1a + src);
            float4 vb = *(const float4*)(w1b + src);
            ta[r][cq*4+0]=va.x; ta[r][cq*4+1]=va.y; ta[r][cq*4+2]=va.z; ta[r][cq*4+3]=va.w;
            tb[r][cq*4+0]=vb.x; tb[r][cq*4+1]=vb.y; tb[r][cq*4+2]=vb.z; tb[r][cq*4+3]=vb.w;
        }
        __syncthreads();
        {
            int n = tid >> 2, kq = tid & 3;
            int side = n >> 5, fl = n & 31;
            union { __nv_bfloat16 b[8]; uint4 u; } h8, l8;
            #pragma unroll
            for (int j = 0; j < 8; j++) {
                float v = side ? tb[kq * 8 + j][fl] : ta[kq * 8 + j][fl];
                split_bf16(v, h8.b[j], l8.b[j]);
            }
            int orow = side ? (128 + ft * 32 + fl) : (ft * 32 + fl);
            size_t off = ((size_t)leaf * 256 + orow) * 512 + kt * 32 + kq * 8;
            *(uint4*)(g_w1t_hi + off) = h8.u;
            *(uint4*)(g_w1t_lo + off) = l8.u;
        }
    } else {            // ---- W2: leaf/dt/kt ----
        const int b2i = bid - 512;
        const int leaf = b2i >> 6, rem = b2i & 63, dt = rem >> 2, kt = rem & 3;
        __shared__ float t[32][33];
        {
            int r = tid >> 3, cq = tid & 7;
            size_t src = ((size_t)leaf * 128 + kt * 32 + r) * 512 + dt * 32 + cq * 4;
            float4 v = *(const float4*)(w2 + src);
            t[r][cq*4+0]=v.x; t[r][cq*4+1]=v.y; t[r][cq*4+2]=v.z; t[r][cq*4+3]=v.w;
        }
        __syncthreads();
        {
            int n = tid >> 3, kq = tid & 7;
            union { __nv_bfloat16 b[4]; uint2 u; } h4, l4;
            #pragma unroll
            for (int j = 0; j < 4; j++) split_bf16(t[kq * 4 + j][n], h4.b[j], l4.b[j]);
            size_t orow = ((size_t)leaf * 512 + dt * 32 + n) * 128 + kt * 32 + kq * 4;
            *(uint2*)(g_w2t_hi + orow) = h4.u;
            *(uint2*)(g_w2t_lo + orow) = l4.u;
        }
    }
}

// ---------------- routing + X split ----------------
__device__ __forceinline__ float warp_sum(float v) {
    #pragma unroll
    for (int o = 16; o > 0; o >>= 1) v += __shfl_xor_sync(0xFFFFFFFFu, v, o);
    return v;
}

__global__ void route_kernel(const float* __restrict__ x,
                             const float* __restrict__ wn0, const float* __restrict__ bn0,
                             const float* __restrict__ wn1, const float* __restrict__ bn1,
                             const float* __restrict__ wn2, const float* __restrict__ bn2)
{
    int gwarp = (blockIdx.x * blockDim.x + threadIdx.x) >> 5;
    int lane  = threadIdx.x & 31;
    if (gwarp >= TOKENS) return;

    const float4* xr4 = (const float4*)(x + (size_t)gwarp * DIM);
    float4 xv[4];
    #pragma unroll
    for (int i = 0; i < 4; i++) xv[i] = xr4[lane + i * 32];

    {
        __nv_bfloat16* xh = g_x_hi + (size_t)gwarp * DIM;
        __nv_bfloat16* xl = g_x_lo + (size_t)gwarp * DIM;
        #pragma unroll
        for (int i = 0; i < 4; i++) {
            float v[4] = { xv[i].x, xv[i].y, xv[i].z, xv[i].w };
            union { __nv_bfloat16 b[4]; uint2 u; } h4, l4;
            #pragma unroll
            for (int j = 0; j < 4; j++) split_bf16(v[j], h4.b[j], l4.b[j]);
            *(uint2*)(xh + (lane + i * 32) * 4) = h4.u;
            *(uint2*)(xl + (lane + i * 32) * 4) = l4.u;
        }
    }

    float s = 0.f;
    #pragma unroll
    for (int i = 0; i < 4; i++) {
        int base = (lane + i * 32) * 4;
        s += xv[i].x * wn0[base + 0] + xv[i].y * wn0[base + 1]
           + xv[i].z * wn0[base + 2] + xv[i].w * wn0[base + 3];
    }
    s = warp_sum(s) + bn0[0];
    int node = (s > 0.f) ? 0 : 1;

    s = 0.f;
    #pragma unroll
    for (int i = 0; i < 4; i++) {
        int base = (lane + i * 32) * 4;
        s += xv[i].x * wn1[(base + 0) * 2 + node] + xv[i].y * wn1[(base + 1) * 2 + node]
           + xv[i].z * wn1[(base + 2) * 2 + node] + xv[i].w * wn1[(base + 3) * 2 + node];
    }
    s = warp_sum(s) + bn1[node];
    node = node * 2 + ((s > 0.f) ? 0 : 1);

    s = 0.f;
    #pragma unroll
    for (int i = 0; i < 4; i++) {
        int base = (lane + i * 32) * 4;
        s += xv[i].x * wn2[(base + 0) * 4 + node] + xv[i].y * wn2[(base + 1) * 4 + node]
           + xv[i].z * wn2[(base + 2) * 4 + node] + xv[i].w * wn2[(base + 3) * 4 + node];
    }
    s = warp_sum(s) + bn2[node];
    int leaf = node * 2 + ((s > 0.f) ? 0 : 1);

    if (lane == 0) {
        int pos = atomicAdd(&g_count[leaf], 1);
        g_list[leaf * TOKENS + pos] = gwarp;
    }
}

// ---------------- SMEM layout ----------------
#define SM_ROWTOK  0
#define SM_B1A     256
#define SM_B1B     768
#define SM_B2      1280
#define SM_X       4096                     // 2 buf x (hi 8KB | lo 8KB) = 32KB
#define SM_W       36864                    // 2 buf x (hi 32KB | lo 32KB) = 128KB
#define SM_H       167936                   // hi0,hi1 (16KB) then lo0,lo1 (16KB)
#define SMEM_TOTAL 200704

#define XHI(p) (sb + SM_X + (p) * 16384)
#define XLO(p) (sb + SM_X + (p) * 16384 + 8192)
#define WHI(p) (sb + SM_W + (p) * 65536)
#define WLO(p) (sb + SM_W + (p) * 65536 + 32768)
#define HHI(k) (sb + SM_H + (k) * 8192)
#define HLO(k) (sb + SM_H + 16384 + (k) * 8192)

// ---------------- fused leaf FFN ----------------
__global__ void __launch_bounds__(THREADS, 1)
ffn_kernel(const float* __restrict__ b1a, const float* __restrict__ b1b,
           const float* __restrict__ b2,  float* __restrict__ out)
{
    extern __shared__ char smem[];
    const uint32_t sb = smem_u32(smem);
    const int tid  = threadIdx.x;
    const int wid  = tid >> 5;
    const int lane = tid & 31;

    const int leaf  = blockIdx.x;
    const int cnt   = g_count[leaf];
    const int start = blockIdx.y * BM;
    if (start >= cnt) return;
    const int rows = min(BM, cnt - start);
    const int* list = g_list + leaf * TOKENS + start;

    int* rowTok = (int*)(smem + SM_ROWTOK);
    if (tid < BM) rowTok[tid] = list[min(tid, rows - 1)];
    {
        float* sB1a = (float*)(smem + SM_B1A);
        float* sB1b = (float*)(smem + SM_B1B);
        float* sB2  = (float*)(smem + SM_B2);
        if (tid < FDIM) { sB1a[tid] = b1a[leaf * FDIM + tid]; sB1b[tid] = b1b[leaf * FDIM + tid]; }
        if (tid < DIM)  sB2[tid] = b2[leaf * DIM + tid];
    }
    __syncthreads();

    const int wm = wid & 3;        // m-block: rows 16*wm..+15
    const int wn = wid >> 2;       // n-block
    const int gid = lane >> 2, tig = lane & 3;
    const int a_row = lane & 15;
    const int a_kad = (lane & 16) >> 1;
    const int b_row = (lane & 7) | ((lane >> 1) & 8);
    const int b_kad = lane & 8;
    const uint32_t arow_off = (uint32_t)((16 * wm + a_row) * 128);

    // GEMM1 B rows: a-cols at rows 32wn+16nt (nt 0,1), b-cols at 128+32wn+16nt (nt 2,3)
    const int br1[4] = { 32 * wn + b_row, 32 * wn + 16 + b_row,
                         128 + 32 * wn + b_row, 128 + 32 * wn + 16 + b_row };
    const int br2[4] = { 64 * wn + b_row, 64 * wn + 16 + b_row,
                         64 * wn + 32 + b_row, 64 * wn + 48 + b_row };

    // ---- chunk loader: c 0..7 = GEMM1 (X + W1), c 8..11 = GEMM2 (W2) ----
    const int xrow = tid >> 3, xq = tid & 7;
    auto issue = [&](int c) {
        const int p = c & 1;
        if (c < 8) {
            const int k0 = c * 64;
            const __nv_bfloat16* xh = g_x_hi + (size_t)rowTok[xrow] * DIM + k0;
            const __nv_bfloat16* xl = g_x_lo + (size_t)rowTok[xrow] * DIM + k0;
            uint32_t so = sw128((uint32_t)(xrow * 128 + xq * 16));
            cpa16(XHI(p) + so, xh + xq * 8);
            cpa16(XLO(p) + so, xl + xq * 8);
            const __nv_bfloat16* whb = g_w1t_hi + (size_t)leaf * 256 * DIM + k0;
            const __nv_bfloat16* wlb = g_w1t_lo + (size_t)leaf * 256 * DIM + k0;
            #pragma unroll
            for (int it = 0; it < 4; it++) {
                int idx = tid + it * THREADS;
                int wrow = idx >> 3, q = idx & 7;
                uint32_t wo = sw128((uint32_t)(wrow * 128 + q * 16));
                cpa16(WHI(p) + wo, whb + (size_t)wrow * DIM + q * 8);
                cpa16(WLO(p) + wo, wlb + (size_t)wrow * DIM + q * 8);
            }
        } else {
            const int idx4 = c - 8, nh = idx4 >> 1, c2 = idx4 & 1;
            const __nv_bfloat16* whb = g_w2t_hi + ((size_t)(leaf * 512 + nh * 256)) * FDIM + c2 * 64;
            const __nv_bfloat16* wlb = g_w2t_lo + ((size_t)(leaf * 512 + nh * 256)) * FDIM + c2 * 64;
            #pragma unroll
            for (int it = 0; it < 4; it++) {
                int idx = tid + it * THREADS;
                int wrow = idx >> 3, q = idx & 7;
                uint32_t wo = sw128((uint32_t)(wrow * 128 + q * 16));
                cpa16(WHI(p) + wo, whb + (size_t)wrow * FDIM + q * 8);
                cpa16(WLO(p) + wo, wlb + (size_t)wrow * FDIM + q * 8);
            }
        }
        CP_COMMIT();
    };

    issue(0);

    // ================= phase 1: GEMM1 (chunks 0..7) =================
    {
        float acc[8][4];
        #pragma unroll
        for (int t = 0; t < 8; t++)
            #pragma unroll
            for (int j = 0; j < 4; j++) acc[t][j] = 0.f;

        for (int c = 0; c < 8; c++) {
            const int p = c & 1;
            issue(c + 1);
            CP_WAIT(1);
            __syncthreads();
            run_chunk(acc, XHI(p), XLO(p), WHI(p), WLO(p), arow_off, br1, a_kad, b_kad);
            __syncthreads();
        }

        // epilogue1: gate (a tile nt, b tile nt+2) -> H bf16 hi/lo, packed 4B stores
        const float* sB1a = (const float*)(smem + SM_B1A);
        const float* sB1b = (const float*)(smem + SM_B1B);
        const int r0 = 16 * wm + gid;
        #pragma unroll
        for (int nt = 0; nt < 2; nt++) {
            #pragma unroll
            for (int q = 0; q < 2; q++) {
                const int f = 32 * wn + 16 * nt + 8 * q + 2 * tig;   // even, pair (f, f+1)
                const float* A = acc[2 * nt + q];
                const float* G = acc[2 * nt + 4 + q];
                const float ba0 = sB1a[f], ba1 = sB1a[f + 1];
                const float bb0 = sB1b[f], bb1 = sB1b[f + 1];
                const float h00 = (A[0] + ba0) * (G[0] + bb0);
                const float h01 = (A[1] + ba1) * (G[1] + bb1);
                const float h10 = (A[2] + ba0) * (G[2] + bb0);
                const float h11 = (A[3] + ba1) * (G[3] + bb1);
                const int kc = f >> 6, fk = f & 63;
                char* hh = smem + (HHI(kc) - sb);
                char* hl = smem + (HLO(kc) - sb);
                const uint32_t o0 = sw128((uint32_t)(r0 * 128 + fk * 2));
                const uint32_t o1 = sw128((uint32_t)((r0 + 8) * 128 + fk * 2));
                __nv_bfloat16 h0h, h0l, h1h, h1l, h2h, h2l, h3h, h3l;
                split_bf16(h00, h0h, h0l);  split_bf16(h01, h1h, h1l);
                split_bf16(h10, h2h, h2l);  split_bf16(h11, h3h, h3l);
                *(uint32_t*)(hh + o0) = pack_bf16x2(h0h, h1h);
                *(uint32_t*)(hl + o0) = pack_bf16x2(h0l, h1l);
                *(uint32_t*)(hh + o1) = pack_bf16x2(h2h, h3h);
                *(uint32_t*)(hl + o1) = pack_bf16x2(h2l, h3l);
            }
        }
    }

    // ================= phase 2: GEMM2 (chunks 8..11) =================
    {
        const float* sB2 = (const float*)(smem + SM_B2);
        int c = 8;
        for (int nh = 0; nh < 2; nh++) {
            float acc2[8][4];
            #pragma unroll
            for (int t = 0; t < 8; t++)
                #pragma unroll
                for (int j = 0; j < 4; j++) acc2[t][j] = 0.f;

            #pragma unroll
            for (int c2 = 0; c2 < 2; c2++, c++) {
                const int p = c & 1;
                if (c < 11) { issue(c + 1); CP_WAIT(1); } else { CP_WAIT(0); }
                __syncthreads();   // also orders epilogue1's H writes before first H read
                run_chunk(acc2, HHI(c2), HLO(c2), WHI(p), WLO(p), arow_off, br2, a_kad, b_kad);
                __syncthreads();
            }

            const int r0 = 16 * wm + gid;
            #pragma unroll
            for (int t = 0; t < 8; t++) {
                const int col = nh * 256 + 64 * wn + 8 * t + 2 * tig;
                const float c0 = sB2[col], c1 = sB2[col + 1];
                if (r0 < rows) {
                    float2 v = { acc2[t][0] + c0, acc2[t][1] + c1 };
                    *(float2*)(out + (size_t)rowTok[r0] * DIM + col) = v;
                }
                if (r0 + 8 < rows) {
                    float2 v = { acc2[t][2] + c0, acc2[t][3] + c1 };
                    *(float2*)(out + (size_t)rowTok[r0 + 8] * DIM + col) = v;
                }
            }
        }
    }
}

extern "C" void kernel_launch(void* const* d_in, const int* in_sizes, int n_in,
                              void* d_out, int out_size)
{
    const float* x   = (const float*)d_in[0];
    const float* wn0 = (const float*)d_in[2];
    const float* bn0 = (const float*)d_in[3];
    const float* wn1 = (const float*)d_in[4];
    const float* bn1 = (const float*)d_in[5];
    const float* wn2 = (const float*)d_in[6];
    const float* bn2 = (const float*)d_in[7];
    const float* w1a = (const float*)d_in[8];
    const float* b1a = (const float*)d_in[9];
    const float* w1b = (const float*)d_in[10];
    const float* b1b = (const float*)d_in[11];
    const float* w2  = (const float*)d_in[12];
    const float* b2  = (const float*)d_in[13];
    float* out = (float*)d_out;

    static_assert(SMEM_TOTAL <= 227 * 1024, "smem");
    cudaFuncSetAttribute(ffn_kernel, cudaFuncAttributeMaxDynamicSharedMemorySize, SMEM_TOTAL);

    prep_kernel<<<1024, 256>>>(w1a, w1b, w2);            // also zeroes g_count
    route_kernel<<<(TOKENS * 32) / 256, 256>>>(x, wn0, bn0, wn1, bn1, wn2, bn2);
    dim3 grid(NLEAF, MAXTILES);
    ffn_kernel<<<grid, THREADS, SMEM_TOTAL>>>(b1a, b1b, b2, out);
}

// round 8
// speedup vs baseline: 2.5886x; 1.3160x over previous
#include <cuda_runtime.h>
#include <cuda_fp16.h>
#include <cstdint>

#define TOKENS   8192
#define DIM      512
#define FDIM     128
#define NLEAF    8
#define BM       64
#define MAXTILES 32
#define THREADS  256

// ---------------- scratch ----------------
__device__ int g_count[NLEAF];
__device__ int g_list[NLEAF * TOKENS];
__device__ __half g_x_hi[TOKENS * DIM];
__device__ __half g_x_lo[TOKENS * DIM];
// W1 transposed fp16: [leaf][n=256][k=512]; n<128 -> w1a col n, n>=128 -> w1b col n-128
__device__ __half g_w1t[NLEAF * 256 * 512];
// W2 transposed fp16: [leaf][n=512][k=128]
__device__ __half g_w2t[NLEAF * 512 * 128];

__device__ __forceinline__ uint32_t smem_u32(const void* p) {
    uint32_t a;
    asm("{ .reg .u64 t; cvta.to.shared.u64 t, %1; cvt.u32.u64 %0, t; }" : "=r"(a) : "l"(p));
    return a;
}
__device__ __forceinline__ uint32_t sw128(uint32_t off) { return off ^ ((off >> 3) & 0x70); }

__device__ __forceinline__ void split_f16(float v, __half& h, __half& l) {
    h = __float2half(v);
    l = __float2half(v - __half2float(h));
}
__device__ __forceinline__ uint32_t pack_f16x2(__half a, __half b) {
    union { __half h[2]; uint32_t u; } t;
    t.h[0] = a; t.h[1] = b;
    return t.u;
}

__device__ __forceinline__ void cpa16(uint32_t dst, const void* src) {
    asm volatile("cp.async.cg.shared.global [%0], [%1], 16;" :: "r"(dst), "l"(src) : "memory");
}
#define CP_COMMIT() asm volatile("cp.async.commit_group;" ::: "memory")
#define CP_WAIT(n)  asm volatile("cp.async.wait_group %0;" :: "n"(n) : "memory")

#define LDSM4(r, a)                                                                   \
    asm volatile("ldmatrix.sync.aligned.m8n8.x4.shared.b16 {%0,%1,%2,%3}, [%4];"     \
        : "=r"((r)[0]), "=r"((r)[1]), "=r"((r)[2]), "=r"((r)[3]) : "r"(a))

__device__ __forceinline__ void mma_f16(float* d, const uint32_t* a, uint32_t b0, uint32_t b1) {
    asm volatile(
        "mma.sync.aligned.m16n8k16.row.col.f32.f16.f16.f32 "
        "{%0,%1,%2,%3},{%4,%5,%6,%7},{%8,%9},{%0,%1,%2,%3};"
        : "+f"(d[0]), "+f"(d[1]), "+f"(d[2]), "+f"(d[3])
        : "r"(a[0]), "r"(a[1]), "r"(a[2]), "r"(a[3]), "r"(b0), "r"(b1));
}

// Fused 2-pass chunk, crossbar/tensor balanced: per kof -> 8 LDSM4, 32 HMMA.
__device__ __forceinline__ void run_fused(
    float acc[2][8][4], uint32_t AH, uint32_t AL, uint32_t B,
    uint32_t arow0, const int br[4], int a_kad, int b_kad)
{
    #pragma unroll
    for (int kof = 0; kof < 64; kof += 16) {
        uint32_t ah[2][4], al[2][4], bf[4][4];
        #pragma unroll
        for (int mt = 0; mt < 2; mt++) {
            const uint32_t ao = sw128(arow0 + mt * 2048 + (kof + a_kad) * 2);
            LDSM4(ah[mt], AH + ao);
            LDSM4(al[mt], AL + ao);
        }
        #pragma unroll
        for (int nt = 0; nt < 4; nt++)
            LDSM4(bf[nt], B + sw128((uint32_t)(br[nt] * 128 + (kof + b_kad) * 2)));
        #pragma unroll
        for (int pass = 0; pass < 2; pass++) {
            #pragma unroll
            for (int mt = 0; mt < 2; mt++) {
                const uint32_t* af = pass ? al[mt] : ah[mt];
                #pragma unroll
                for (int nt = 0; nt < 4; nt++) {
                    mma_f16(acc[mt][2 * nt],     af, bf[nt][0], bf[nt][1]);
                    mma_f16(acc[mt][2 * nt + 1], af, bf[nt][2], bf[nt][3]);
                }
            }
        }
    }
}

// ---------------- prep: zero counters + transpose W1/W2 to fp16 ----------------
__global__ void prep_kernel(const float* __restrict__ w1a, const float* __restrict__ w1b,
                            const float* __restrict__ w2) {
    const int bid = blockIdx.x;
    const int tid = threadIdx.x;
    if (bid == 0 && tid < NLEAF) g_count[tid] = 0;

    if (bid < 512) {    // ---- W1: leaf/kt/ft ----
        const int leaf = bid >> 6, rem = bid & 63, kt = rem >> 2, ft = rem & 3;
        __shared__ float ta[32][33], tb[32][33];
        {
            int r = tid >> 3, cq = tid & 7;
            size_t src = ((size_t)leaf * 512 + kt * 32 + r) * 128 + ft * 32 + cq * 4;
            float4 va = *(const float4*)(w1a + src);
            float4 vb = *(const float4*)(w1b + src);
            ta[r][cq*4+0]=va.x; ta[r][cq*4+1]=va.y; ta[r][cq*4+2]=va.z; ta[r][cq*4+3]=va.w;
            tb[r][cq*4+0]=vb.x; tb[r][cq*4+1]=vb.y; tb[r][cq*4+2]=vb.z; tb[r][cq*4+3]=vb.w;
        }
        __syncthreads();
        {
            int n = tid >> 2, kq = tid & 3;
            int side = n >> 5, fl = n & 31;
            union { __half h[8]; uint4 u; } h8;
            #pragma unroll
            for (int j = 0; j < 8; j++) {
                float v = side ? tb[kq * 8 + j][fl] : ta[kq * 8 + j][fl];
                h8.h[j] = __float2half(v);
            }
            int orow = side ? (128 + ft * 32 + fl) : (ft * 32 + fl);
            size_t off = ((size_t)leaf * 256 + orow) * 512 + kt * 32 + kq * 8;
            *(uint4*)(g_w1t + off) = h8.u;
        }
    } else {            // ---- W2: leaf/dt/kt ----
        const int b2i = bid - 512;
        const int leaf = b2i >> 6, rem = b2i & 63, dt = rem >> 2, kt = rem & 3;
        __shared__ float t[32][33];
        {
            int r = tid >> 3, cq = tid & 7;
            size_t src = ((size_t)leaf * 128 + kt * 32 + r) * 512 + dt * 32 + cq * 4;
            float4 v = *(const float4*)(w2 + src);
            t[r][cq*4+0]=v.x; t[r][cq*4+1]=v.y; t[r][cq*4+2]=v.z; t[r][cq*4+3]=v.w;
        }
        __syncthreads();
        {
            int n = tid >> 3, kq = tid & 7;
            union { __half h[4]; uint2 u; } h4;
            #pragma unroll
            for (int j = 0; j < 4; j++) h4.h[j] = __float2half(t[kq * 4 + j][n]);
            size_t orow = ((size_t)leaf * 512 + dt * 32 + n) * 128 + kt * 32 + kq * 4;
            *(uint2*)(g_w2t + orow) = h4.u;
        }
    }
}

// ---------------- routing + X fp16 split ----------------
__device__ __forceinline__ float warp_sum(float v) {
    #pragma unroll
    for (int o = 16; o > 0; o >>= 1) v += __shfl_xor_sync(0xFFFFFFFFu, v, o);
    return v;
}

__global__ void route_kernel(const float* __restrict__ x,
                             const float* __restrict__ wn0, const float* __restrict__ bn0,
                             const float* __restrict__ wn1, const float* __restrict__ bn1,
                             const float* __restrict__ wn2, const float* __restrict__ bn2)
{
    int gwarp = (blockIdx.x * blockDim.x + threadIdx.x) >> 5;
    int lane  = threadIdx.x & 31;
    if (gwarp >= TOKENS) return;

    const float4* xr4 = (const float4*)(x + (size_t)gwarp * DIM);
    float4 xv[4];
    #pragma unroll
    for (int i = 0; i < 4; i++) xv[i] = xr4[lane + i * 32];

    {
        __half* xh = g_x_hi + (size_t)gwarp * DIM;
        __half* xl = g_x_lo + (size_t)gwarp * DIM;
        #pragma unroll
        for (int i = 0; i < 4; i++) {
            float v[4] = { xv[i].x, xv[i].y, xv[i].z, xv[i].w };
            union { __half h[4]; uint2 u; } h4, l4;
            #pragma unroll
            for (int j = 0; j < 4; j++) split_f16(v[j], h4.h[j], l4.h[j]);
            *(uint2*)(xh + (lane + i * 32) * 4) = h4.u;
            *(uint2*)(xl + (lane + i * 32) * 4) = l4.u;
        }
    }

    float s = 0.f;
    #pragma unroll
    for (int i = 0; i < 4; i++) {
        int base = (lane + i * 32) * 4;
        s += xv[i].x * wn0[base + 0] + xv[i].y * wn0[base + 1]
           + xv[i].z * wn0[base + 2] + xv[i].w * wn0[base + 3];
    }
    s = warp_sum(s) + bn0[0];
    int node = (s > 0.f) ? 0 : 1;

    s = 0.f;
    #pragma unroll
    for (int i = 0; i < 4; i++) {
        int base = (lane + i * 32) * 4;
        s += xv[i].x * wn1[(base + 0) * 2 + node] + xv[i].y * wn1[(base + 1) * 2 + node]
           + xv[i].z * wn1[(base + 2) * 2 + node] + xv[i].w * wn1[(base + 3) * 2 + node];
    }
    s = warp_sum(s) + bn1[node];
    node = node * 2 + ((s > 0.f) ? 0 : 1);

    s = 0.f;
    #pragma unroll
    for (int i = 0; i < 4; i++) {
        int base = (lane + i * 32) * 4;
        s += xv[i].x * wn2[(base + 0) * 4 + node] + xv[i].y * wn2[(base + 1) * 4 + node]
           + xv[i].z * wn2[(base + 2) * 4 + node] + xv[i].w * wn2[(base + 3) * 4 + node];
    }
    s = warp_sum(s) + bn2[node];
    int leaf = node * 2 + ((s > 0.f) ? 0 : 1);

    if (lane == 0) {
        int pos = atomicAdd(&g_count[leaf], 1);
        g_list[leaf * TOKENS + pos] = gwarp;
    }
}

// ---------------- SMEM layout ----------------
#define SM_ROWTOK  0
#define SM_B1A     256
#define SM_B1B     768
#define SM_B2      1280
#define SM_X       4096                     // 2 buf x (hi 8KB | lo 8KB) = 32KB
#define SM_W       36864                    // 2 buf x 32KB = 64KB
#define SM_H       102400                   // hi0,hi1 (16KB) then lo0,lo1 (16KB)
#define SMEM_TOTAL 135168

#define XHI(p) (sb + SM_X + (p) * 16384)
#define XLO(p) (sb + SM_X + (p) * 16384 + 8192)
#define WB(p)  (sb + SM_W + (p) * 32768)
#define HHI(k) (sb + SM_H + (k) * 8192)
#define HLO(k) (sb + SM_H + 16384 + (k) * 8192)

// ---------------- fused leaf FFN: fp16 2-pass, balanced tiles ----------------
__global__ void __launch_bounds__(THREADS, 1)
ffn_kernel(const float* __restrict__ b1a, const float* __restrict__ b1b,
           const float* __restrict__ b2,  float* __restrict__ out)
{
    extern __shared__ char smem[];
    const uint32_t sb = smem_u32(smem);
    const int tid  = threadIdx.x;
    const int wid  = tid >> 5;
    const int lane = tid & 31;

    const int leaf  = blockIdx.x;
    const int cnt   = g_count[leaf];
    const int start = blockIdx.y * BM;
    if (start >= cnt) return;
    const int rows = min(BM, cnt - start);
    const int* list = g_list + leaf * TOKENS + start;

    int* rowTok = (int*)(smem + SM_ROWTOK);
    if (tid < BM) rowTok[tid] = list[min(tid, rows - 1)];
    {
        float* sB1a = (float*)(smem + SM_B1A);
        float* sB1b = (float*)(smem + SM_B1B);
        float* sB2  = (float*)(smem + SM_B2);
        if (tid < FDIM) { sB1a[tid] = b1a[leaf * FDIM + tid]; sB1b[tid] = b1b[leaf * FDIM + tid]; }
        for (int i = tid; i < DIM; i += THREADS) sB2[i] = b2[leaf * DIM + i];
    }
    __syncthreads();

    const int wm = wid & 1;        // m-block: rows 32*wm..+31 (2 m-tiles of 16)
    const int wn = wid >> 1;       // n-block 0..3
    const int gid = lane >> 2, tig = lane & 3;
    const int a_row = lane & 15;
    const int a_kad = (lane & 16) >> 1;
    const int b_row = (lane & 7) | ((lane >> 1) & 8);
    const int b_kad = lane & 8;
    const uint32_t arow0 = (uint32_t)((32 * wm + a_row) * 128);

    const int br1[4] = { 32 * wn + b_row, 32 * wn + 16 + b_row,
                         128 + 32 * wn + b_row, 128 + 32 * wn + 16 + b_row };
    const int br2[4] = { 64 * wn + b_row, 64 * wn + 16 + b_row,
                         64 * wn + 32 + b_row, 64 * wn + 48 + b_row };

    // ---- chunk loader: c 0..7 = GEMM1 (X + W1), c 8..11 = GEMM2 (W2) ----
    auto issue = [&](int c) {
        const int p = c & 1;
        if (c < 8) {
            const int k0 = c * 64;
            #pragma unroll
            for (int it = 0; it < 2; it++) {           // X hi+lo: 64 rows x 128B
                int idx = tid + it * THREADS;
                int xrow = idx >> 3, xq = idx & 7;
                const __half* xh = g_x_hi + (size_t)rowTok[xrow] * DIM + k0;
                const __half* xl = g_x_lo + (size_t)rowTok[xrow] * DIM + k0;
                uint32_t so = sw128((uint32_t)(xrow * 128 + xq * 16));
                cpa16(XHI(p) + so, xh + xq * 8);
                cpa16(XLO(p) + so, xl + xq * 8);
            }
            const __half* wb = g_w1t + (size_t)leaf * 256 * DIM + k0;
            #pragma unroll
            for (int it = 0; it < 8; it++) {           // W1: 256 rows x 128B
                int idx = tid + it * THREADS;
                int wrow = idx >> 3, q = idx & 7;
                uint32_t wo = sw128((uint32_t)(wrow * 128 + q * 16));
                cpa16(WB(p) + wo, wb + (size_t)wrow * DIM + q * 8);
            }
        } else {
            const int idx4 = c - 8, nh = idx4 >> 1, c2 = idx4 & 1;
            const __half* wb = g_w2t + ((size_t)(leaf * 512 + nh * 256)) * FDIM + c2 * 64;
            #pragma unroll
            for (int it = 0; it < 8; it++) {
                int idx = tid + it * THREADS;
                int wrow = idx >> 3, q = idx & 7;
                uint32_t wo = sw128((uint32_t)(wrow * 128 + q * 16));
                cpa16(WB(p) + wo, wb + (size_t)wrow * FDIM + q * 8);
            }
        }
        CP_COMMIT();
    };

    issue(0);

    // ================= phase 1: GEMM1 (chunks 0..7) =================
    {
        float acc[2][8][4];
        #pragma unroll
        for (int mt = 0; mt < 2; mt++)
            #pragma unroll
            for (int t = 0; t < 8; t++)
                #pragma unroll
                for (int j = 0; j < 4; j++) acc[mt][t][j] = 0.f;

        for (int c = 0; c < 8; c++) {
            const int p = c & 1;
            issue(c + 1);
            CP_WAIT(1);
            __syncthreads();
            run_fused(acc, XHI(p), XLO(p), WB(p), arow0, br1, a_kad, b_kad);
            __syncthreads();
        }

        // epilogue1: gate (a tile nt, b tile nt+2) -> H fp16 hi/lo, packed 4B stores
        const float* sB1a = (const float*)(smem + SM_B1A);
        const float* sB1b = (const float*)(smem + SM_B1B);
        #pragma unroll
        for (int mt = 0; mt < 2; mt++) {
            const int r0 = 32 * wm + 16 * mt + gid;
            #pragma unroll
            for (int nt = 0; nt < 2; nt++) {
                #pragma unroll
                for (int q = 0; q < 2; q++) {
                    const int f = 32 * wn + 16 * nt + 8 * q + 2 * tig;
                    const float* A = acc[mt][2 * nt + q];
                    const float* G = acc[mt][2 * (nt + 2) + q];
                    const float ba0 = sB1a[f], ba1 = sB1a[f + 1];
                    const float bb0 = sB1b[f], bb1 = sB1b[f + 1];
                    const float h00 = (A[0] + ba0) * (G[0] + bb0);
                    const float h01 = (A[1] + ba1) * (G[1] + bb1);
                    const float h10 = (A[2] + ba0) * (G[2] + bb0);
                    const float h11 = (A[3] + ba1) * (G[3] + bb1);
                    const int kc = f >> 6, fk = f & 63;
                    char* hh = smem + (HHI(kc) - sb);
                    char* hl = smem + (HLO(kc) - sb);
                    const uint32_t o0 = sw128((uint32_t)(r0 * 128 + fk * 2));
                    const uint32_t o1 = sw128((uint32_t)((r0 + 8) * 128 + fk * 2));
                    __half a0h, a0l, a1h, a1l, a2h, a2l, a3h, a3l;
                    split_f16(h00, a0h, a0l);  split_f16(h01, a1h, a1l);
                    split_f16(h10, a2h, a2l);  split_f16(h11, a3h, a3l);
                    *(uint32_t*)(hh + o0) = pack_f16x2(a0h, a1h);
                    *(uint32_t*)(hl + o0) = pack_f16x2(a0l, a1l);
                    *(uint32_t*)(hh + o1) = pack_f16x2(a2h, a3h);
                    *(uint32_t*)(hl + o1) = pack_f16x2(a2l, a3l);
                }
            }
        }
    }

    // ================= phase 2: GEMM2 (chunks 8..11) =================
    {
        const float* sB2 = (const float*)(smem + SM_B2);
        int c = 8;
        for (int nh = 0; nh < 2; nh++) {
            float acc2[2][8][4];
            #pragma unroll
            for (int mt = 0; mt < 2; mt++)
                #pragma unroll
                for (int t = 0; t < 8; t++)
                    #pragma unroll
                    for (int j = 0; j < 4; j++) acc2[mt][t][j] = 0.f;

            #pragma unroll
            for (int c2 = 0; c2 < 2; c2++, c++) {
                const int p = c & 1;
                if (c < 11) { issue(c + 1); CP_WAIT(1); } else { CP_WAIT(0); }
                __syncthreads();   // also orders epilogue1's H writes before first H read
                run_fused(acc2, HHI(c2), HLO(c2), WB(p), arow0, br2, a_kad, b_kad);
                __syncthreads();
            }

            #pragma unroll
            for (int mt = 0; mt < 2; mt++) {
                const int r0 = 32 * wm + 16 * mt + gid;
                #pragma unroll
                for (int t = 0; t < 8; t++) {
                    const int col = nh * 256 + 64 * wn + 8 * t + 2 * tig;
                    const float c0 = sB2[col], c1 = sB2[col + 1];
                    if (r0 < rows) {
                        float2 v = { acc2[mt][t][0] + c0, acc2[mt][t][1] + c1 };
                        *(float2*)(out + (size_t)rowTok[r0] * DIM + col) = v;
                    }
                    if (r0 + 8 < rows) {
                        float2 v = { acc2[mt][t][2] + c0, acc2[mt][t][3] + c1 };
                        *(float2*)(out + (size_t)rowTok[r0 + 8] * DIM + col) = v;
                    }
                }
            }
        }
    }
}

extern "C" void kernel_launch(void* const* d_in, const int* in_sizes, int n_in,
                              void* d_out, int out_size)
{
    const float* x   = (const float*)d_in[0];
    const float* wn0 = (const float*)d_in[2];
    const float* bn0 = (const float*)d_in[3];
    const float* wn1 = (const float*)d_in[4];
    const float* bn1 = (const float*)d_in[5];
    const float* wn2 = (const float*)d_in[6];
    const float* bn2 = (const float*)d_in[7];
    const float* w1a = (const float*)d_in[8];
    const float* b1a = (const float*)d_in[9];
    const float* w1b = (const float*)d_in[10];
    const float* b1b = (const float*)d_in[11];
    const float* w2  = (const float*)d_in[12];
    const float* b2  = (const float*)d_in[13];
    float* out = (float*)d_out;

    static_assert(SMEM_TOTAL <= 227 * 1024, "smem");
    cudaFuncSetAttribute(ffn_kernel, cudaFuncAttributeMaxDynamicSharedMemorySize, SMEM_TOTAL);

    prep_kernel<<<1024, 256>>>(w1a, w1b, w2);            // also zeroes g_count
    route_kernel<<<(TOKENS * 32) / 256, 256>>>(x, wn0, bn0, wn1, bn1, wn2, bn2);
    dim3 grid(NLEAF, MAXTILES);
    ffn_kernel<<<grid, THREADS, SMEM_TOTAL>>>(b1a, b1b, b2, out);
}

// round 9
// speedup vs baseline: 2.7928x; 1.0789x over previous
#include <cuda_runtime.h>
#include <cuda_fp16.h>
#include <cstdint>

#define TOKENS   8192
#define DIM      512
#define FDIM     128
#define NLEAF    8
#define BM       64
#define MAXTILES 32
#define THREADS  256
#define TOTAL_CTAS (NLEAF * MAXTILES)

// ---------------- scratch ----------------
__device__ int g_count[NLEAF];          // zero-init at load; re-zeroed by ffn's last CTA
__device__ int g_done;                  // ffn completion counter (self-resetting)
__device__ int g_list[NLEAF * TOKENS];
__device__ __half g_x_hi[TOKENS * DIM];
__device__ __half g_x_lo[TOKENS * DIM];
// W1 transposed fp16: [leaf][n=256][k=512]; n<128 -> w1a col n, n>=128 -> w1b col n-128
__device__ __half g_w1t[NLEAF * 256 * 512];
// W2 transposed fp16: [leaf][n=512][k=128]
__device__ __half g_w2t[NLEAF * 512 * 128];

__device__ __forceinline__ uint32_t smem_u32(const void* p) {
    uint32_t a;
    asm("{ .reg .u64 t; cvta.to.shared.u64 t, %1; cvt.u32.u64 %0, t; }" : "=r"(a) : "l"(p));
    return a;
}
__device__ __forceinline__ uint32_t sw128(uint32_t off) { return off ^ ((off >> 3) & 0x70); }

__device__ __forceinline__ void split_f16(float v, __half& h, __half& l) {
    h = __float2half(v);
    l = __float2half(v - __half2float(h));
}
__device__ __forceinline__ uint32_t pack_f16x2(__half a, __half b) {
    union { __half h[2]; uint32_t u; } t;
    t.h[0] = a; t.h[1] = b;
    return t.u;
}

__device__ __forceinline__ void cpa16(uint32_t dst, const void* src) {
    asm volatile("cp.async.cg.shared.global [%0], [%1], 16;" :: "r"(dst), "l"(src) : "memory");
}
#define CP_COMMIT() asm volatile("cp.async.commit_group;" ::: "memory")
#define CP_WAIT(n)  asm volatile("cp.async.wait_group %0;" :: "n"(n) : "memory")

#define LDSM4(r, a)                                                                   \
    asm volatile("ldmatrix.sync.aligned.m8n8.x4.shared.b16 {%0,%1,%2,%3}, [%4];"     \
        : "=r"((r)[0]), "=r"((r)[1]), "=r"((r)[2]), "=r"((r)[3]) : "r"(a))

__device__ __forceinline__ void mma_f16(float* d, const uint32_t* a, uint32_t b0, uint32_t b1) {
    asm volatile(
        "mma.sync.aligned.m16n8k16.row.col.f32.f16.f16.f32 "
        "{%0,%1,%2,%3},{%4,%5,%6,%7},{%8,%9},{%0,%1,%2,%3};"
        : "+f"(d[0]), "+f"(d[1]), "+f"(d[2]), "+f"(d[3])
        : "r"(a[0]), "r"(a[1]), "r"(a[2]), "r"(a[3]), "r"(b0), "r"(b1));
}

// Fused 2-pass chunk, crossbar/tensor balanced: per kof -> 8 LDSM4, 32 HMMA.
__device__ __forceinline__ void run_fused(
    float acc[2][8][4], uint32_t AH, uint32_t AL, uint32_t B,
    uint32_t arow0, const int br[4], int a_kad, int b_kad)
{
    #pragma unroll
    for (int kof = 0; kof < 64; kof += 16) {
        uint32_t ah[2][4], al[2][4], bf[4][4];
        #pragma unroll
        for (int mt = 0; mt < 2; mt++) {
            const uint32_t ao = sw128(arow0 + mt * 2048 + (kof + a_kad) * 2);
            LDSM4(ah[mt], AH + ao);
            LDSM4(al[mt], AL + ao);
        }
        #pragma unroll
        for (int nt = 0; nt < 4; nt++)
            LDSM4(bf[nt], B + sw128((uint32_t)(br[nt] * 128 + (kof + b_kad) * 2)));
        #pragma unroll
        for (int pass = 0; pass < 2; pass++) {
            #pragma unroll
            for (int mt = 0; mt < 2; mt++) {
                const uint32_t* af = pass ? al[mt] : ah[mt];
                #pragma unroll
                for (int nt = 0; nt < 4; nt++) {
                    mma_f16(acc[mt][2 * nt],     af, bf[nt][0], bf[nt][1]);
                    mma_f16(acc[mt][2 * nt + 1], af, bf[nt][2], bf[nt][3]);
                }
            }
        }
    }
}

__device__ __forceinline__ float warp_sum(float v) {
    #pragma unroll
    for (int o = 16; o > 0; o >>= 1) v += __shfl_xor_sync(0xFFFFFFFFu, v, o);
    return v;
}

// ---------------- fused prep (W transpose->fp16) + routing + X split ----------------
// blocks [0,512): W1; [512,1024): W2; [1024,2048): route (8 tokens per block).
__global__ void prep_route_kernel(
    const float* __restrict__ w1a, const float* __restrict__ w1b, const float* __restrict__ w2,
    const float* __restrict__ x,
    const float* __restrict__ wn0, const float* __restrict__ bn0,
    const float* __restrict__ wn1, const float* __restrict__ bn1,
    const float* __restrict__ wn2, const float* __restrict__ bn2)
{
    const int bid = blockIdx.x;
    const int tid = threadIdx.x;

    if (bid < 512) {        // ---- W1: leaf/kt/ft ----
        const int leaf = bid >> 6, rem = bid & 63, kt = rem >> 2, ft = rem & 3;
        __shared__ float ta[32][33], tb[32][33];
        {
            int r = tid >> 3, cq = tid & 7;
            size_t src = ((size_t)leaf * 512 + kt * 32 + r) * 128 + ft * 32 + cq * 4;
            float4 va = *(const float4*)(w1a + src);
            float4 vb = *(const float4*)(w1b + src);
            ta[r][cq*4+0]=va.x; ta[r][cq*4+1]=va.y; ta[r][cq*4+2]=va.z; ta[r][cq*4+3]=va.w;
            tb[r][cq*4+0]=vb.x; tb[r][cq*4+1]=vb.y; tb[r][cq*4+2]=vb.z; tb[r][cq*4+3]=vb.w;
        }
        __syncthreads();
        {
            int n = tid >> 2, kq = tid & 3;
            int side = n >> 5, fl = n & 31;
            union { __half h[8]; uint4 u; } h8;
            #pragma unroll
            for (int j = 0; j < 8; j++) {
                float v = side ? tb[kq * 8 + j][fl] : ta[kq * 8 + j][fl];
                h8.h[j] = __float2half(v);
            }
            int orow = side ? (128 + ft * 32 + fl) : (ft * 32 + fl);
            size_t off = ((size_t)leaf * 256 + orow) * 512 + kt * 32 + kq * 8;
            *(uint4*)(g_w1t + off) = h8.u;
        }
    } else if (bid < 1024) {    // ---- W2: leaf/dt/kt ----
        const int b2i = bid - 512;
        const int leaf = b2i >> 6, rem = b2i & 63, dt = rem >> 2, kt = rem & 3;
        __shared__ float t[32][33];
        {
            int r = tid >> 3, cq = tid & 7;
            size_t src = ((size_t)leaf * 128 + kt * 32 + r) * 512 + dt * 32 + cq * 4;
            float4 v = *(const float4*)(w2 + src);
            t[r][cq*4+0]=v.x; t[r][cq*4+1]=v.y; t[r][cq*4+2]=v.z; t[r][cq*4+3]=v.w;
        }
        __syncthreads();
        {
            int n = tid >> 3, kq = tid & 7;
            union { __half h[4]; uint2 u; } h4;
            #pragma unroll
            for (int j = 0; j < 4; j++) h4.h[j] = __float2half(t[kq * 4 + j][n]);
            size_t orow = ((size_t)leaf * 512 + dt * 32 + n) * 128 + kt * 32 + kq * 4;
            *(uint2*)(g_w2t + orow) = h4.u;
        }
    } else {                // ---- route: one warp per token ----
        const int gwarp = (bid - 1024) * 8 + (tid >> 5);
        const int lane  = tid & 31;

        const float4* xr4 = (const float4*)(x + (size_t)gwarp * DIM);
        float4 xv[4];
        #pragma unroll
        for (int i = 0; i < 4; i++) xv[i] = xr4[lane + i * 32];

        {
            __half* xh = g_x_hi + (size_t)gwarp * DIM;
            __half* xl = g_x_lo + (size_t)gwarp * DIM;
            #pragma unroll
            for (int i = 0; i < 4; i++) {
                float v[4] = { xv[i].x, xv[i].y, xv[i].z, xv[i].w };
                union { __half h[4]; uint2 u; } h4, l4;
                #pragma unroll
                for (int j = 0; j < 4; j++) split_f16(v[j], h4.h[j], l4.h[j]);
                *(uint2*)(xh + (lane + i * 32) * 4) = h4.u;
                *(uint2*)(xl + (lane + i * 32) * 4) = l4.u;
            }
        }

        float s = 0.f;
        #pragma unroll
        for (int i = 0; i < 4; i++) {
            int base = (lane + i * 32) * 4;
            s += xv[i].x * wn0[base + 0] + xv[i].y * wn0[base + 1]
               + xv[i].z * wn0[base + 2] + xv[i].w * wn0[base + 3];
        }
        s = warp_sum(s) + bn0[0];
        int node = (s > 0.f) ? 0 : 1;

        s = 0.f;
        #pragma unroll
        for (int i = 0; i < 4; i++) {
            int base = (lane + i * 32) * 4;
            s += xv[i].x * wn1[(base + 0) * 2 + node] + xv[i].y * wn1[(base + 1) * 2 + node]
               + xv[i].z * wn1[(base + 2) * 2 + node] + xv[i].w * wn1[(base + 3) * 2 + node];
        }
        s = warp_sum(s) + bn1[node];
        node = node * 2 + ((s > 0.f) ? 0 : 1);

        s = 0.f;
        #pragma unroll
        for (int i = 0; i < 4; i++) {
            int base = (lane + i * 32) * 4;
            s += xv[i].x * wn2[(base + 0) * 4 + node] + xv[i].y * wn2[(base + 1) * 4 + node]
               + xv[i].z * wn2[(base + 2) * 4 + node] + xv[i].w * wn2[(base + 3) * 4 + node];
        }
        s = warp_sum(s) + bn2[node];
        int leaf = node * 2 + ((s > 0.f) ? 0 : 1);

        if (lane == 0) {
            int pos = atomicAdd(&g_count[leaf], 1);
            g_list[leaf * TOKENS + pos] = gwarp;
        }
    }
}

// ---------------- SMEM layout: 3-stage pipeline ----------------
#define SM_ROWTOK  0
#define SM_B1A     256
#define SM_B1B     768
#define SM_B2      1280
#define SM_X       4096                     // 3 buf x (hi 8KB | lo 8KB) = 48KB
#define SM_W       53248                    // 3 buf x 32KB = 96KB
#define SM_H       151552                   // hi0,hi1 (16KB) then lo0,lo1 (16KB)
#define SMEM_TOTAL 184320

#define XHI(p) (sb + SM_X + (p) * 16384)
#define XLO(p) (sb + SM_X + (p) * 16384 + 8192)
#define WB(p)  (sb + SM_W + (p) * 32768)
#define HHI(k) (sb + SM_H + (k) * 8192)
#define HLO(k) (sb + SM_H + 16384 + (k) * 8192)

__device__ __forceinline__ void cta_done_and_maybe_reset() {
    int old = atomicAdd(&g_done, 1);
    if (old == TOTAL_CTAS - 1) {
        #pragma unroll
        for (int i = 0; i < NLEAF; i++) g_count[i] = 0;
        __threadfence();
        g_done = 0;
    }
}

// ---------------- fused leaf FFN: fp16 2-pass, 3-stage pipeline, 1 sync/chunk ----------------
__global__ void __launch_bounds__(THREADS, 1)
ffn_kernel(const float* __restrict__ b1a, const float* __restrict__ b1b,
           const float* __restrict__ b2,  float* __restrict__ out)
{
    extern __shared__ char smem[];
    const uint32_t sb = smem_u32(smem);
    const int tid  = threadIdx.x;
    const int wid  = tid >> 5;
    const int lane = tid & 31;

    const int leaf  = blockIdx.x;
    const int cnt   = g_count[leaf];
    const int start = blockIdx.y * BM;
    if (start >= cnt) {
        __syncthreads();                     // all threads have read g_count
        if (tid == 0) cta_done_and_maybe_reset();
        return;
    }
    const int rows = min(BM, cnt - start);
    const int* list = g_list + leaf * TOKENS + start;

    int* rowTok = (int*)(smem + SM_ROWTOK);
    if (tid < BM) rowTok[tid] = list[min(tid, rows - 1)];
    {
        float* sB1a = (float*)(smem + SM_B1A);
        float* sB1b = (float*)(smem + SM_B1B);
        float* sB2  = (float*)(smem + SM_B2);
        if (tid < FDIM) { sB1a[tid] = b1a[leaf * FDIM + tid]; sB1b[tid] = b1b[leaf * FDIM + tid]; }
        for (int i = tid; i < DIM; i += THREADS) sB2[i] = b2[leaf * DIM + i];
    }
    __syncthreads();

    const int wm = wid & 1;
    const int wn = wid >> 1;
    const int gid = lane >> 2, tig = lane & 3;
    const int a_row = lane & 15;
    const int a_kad = (lane & 16) >> 1;
    const int b_row = (lane & 7) | ((lane >> 1) & 8);
    const int b_kad = lane & 8;
    const uint32_t arow0 = (uint32_t)((32 * wm + a_row) * 128);

    const int br1[4] = { 32 * wn + b_row, 32 * wn + 16 + b_row,
                         128 + 32 * wn + b_row, 128 + 32 * wn + 16 + b_row };
    const int br2[4] = { 64 * wn + b_row, 64 * wn + 16 + b_row,
                         64 * wn + 32 + b_row, 64 * wn + 48 + b_row };

    // per-thread X source rows (hoisted: rows tid>>3 and tid>>3 + 32)
    const int xq = tid & 7;
    const size_t tokA = (size_t)rowTok[tid >> 3] * DIM;
    const size_t tokB = (size_t)rowTok[(tid >> 3) + 32] * DIM;
    const __half* w1base = g_w1t + (size_t)leaf * 256 * DIM;
    const __half* w2base = g_w2t + (size_t)leaf * 512 * FDIM;

    auto issue = [&](int c) {
        const int p = c % 3;
        if (c < 8) {
            const int k0 = c * 64;
            {   // X hi+lo: 64 rows x 128B (2 rows per thread)
                const int ra = tid >> 3;
                uint32_t soA = sw128((uint32_t)(ra * 128 + xq * 16));
                uint32_t soB = sw128((uint32_t)((ra + 32) * 128 + xq * 16));
                cpa16(XHI(p) + soA, g_x_hi + tokA + k0 + xq * 8);
                cpa16(XLO(p) + soA, g_x_lo + tokA + k0 + xq * 8);
                cpa16(XHI(p) + soB, g_x_hi + tokB + k0 + xq * 8);
                cpa16(XLO(p) + soB, g_x_lo + tokB + k0 + xq * 8);
            }
            const __half* wb = w1base + k0;
            #pragma unroll
            for (int it = 0; it < 8; it++) {           // W1: 256 rows x 128B
                int idx = tid + it * THREADS;
                int wrow = idx >> 3, q = idx & 7;
                uint32_t wo = sw128((uint32_t)(wrow * 128 + q * 16));
                cpa16(WB(p) + wo, wb + (size_t)wrow * DIM + q * 8);
            }
        } else {
            const int idx4 = c - 8, nh = idx4 >> 1, c2 = idx4 & 1;
            const __half* wb = w2base + (size_t)nh * 256 * FDIM + c2 * 64;
            #pragma unroll
            for (int it = 0; it < 8; it++) {
                int idx = tid + it * THREADS;
                int wrow = idx >> 3, q = idx & 7;
                uint32_t wo = sw128((uint32_t)(wrow * 128 + q * 16));
                cpa16(WB(p) + wo, wb + (size_t)wrow * FDIM + q * 8);
            }
        }
        CP_COMMIT();
    };

    issue(0);
    issue(1);

    // ================= phase 1: GEMM1 (chunks 0..7) =================
    {
        float acc[2][8][4];
        #pragma unroll
        for (int mt = 0; mt < 2; mt++)
            #pragma unroll
            for (int t = 0; t < 8; t++)
                #pragma unroll
                for (int j = 0; j < 4; j++) acc[mt][t][j] = 0.f;

        for (int c = 0; c < 8; c++) {
            const int p = c % 3;
            CP_WAIT(1);                      // chunk c landed
            __syncthreads();                 // all warps past run_fused(c-1)
            issue(c + 2);                    // writes buf (c+2)%3 == (c-1)%3, now free
            run_fused(acc, XHI(p), XLO(p), WB(p), arow0, br1, a_kad, b_kad);
        }

        // epilogue1: gate (a tile nt, b tile nt+2) -> H fp16 hi/lo, packed 4B stores
        const float* sB1a = (const float*)(smem + SM_B1A);
        const float* sB1b = (const float*)(smem + SM_B1B);
        #pragma unroll
        for (int mt = 0; mt < 2; mt++) {
            const int r0 = 32 * wm + 16 * mt + gid;
            #pragma unroll
            for (int nt = 0; nt < 2; nt++) {
                #pragma unroll
                for (int q = 0; q < 2; q++) {
                    const int f = 32 * wn + 16 * nt + 8 * q + 2 * tig;
                    const float* A = acc[mt][2 * nt + q];
                    const float* G = acc[mt][2 * (nt + 2) + q];
                    const float ba0 = sB1a[f], ba1 = sB1a[f + 1];
                    const float bb0 = sB1b[f], bb1 = sB1b[f + 1];
                    const float h00 = (A[0] + ba0) * (G[0] + bb0);
                    const float h01 = (A[1] + ba1) * (G[1] + bb1);
                    const float h10 = (A[2] + ba0) * (G[2] + bb0);
                    const float h11 = (A[3] + ba1) * (G[3] + bb1);
                    const int kc = f >> 6, fk = f & 63;
                    char* hh = smem + (HHI(kc) - sb);
                    char* hl = smem + (HLO(kc) - sb);
                    const uint32_t o0 = sw128((uint32_t)(r0 * 128 + fk * 2));
                    const uint32_t o1 = sw128((uint32_t)((r0 + 8) * 128 + fk * 2));
                    __half a0h, a0l, a1h, a1l, a2h, a2l, a3h, a3l;
                    split_f16(h00, a0h, a0l);  split_f16(h01, a1h, a1l);
                    split_f16(h10, a2h, a2l);  split_f16(h11, a3h, a3l);
                    *(uint32_t*)(hh + o0) = pack_f16x2(a0h, a1h);
                    *(uint32_t*)(hl + o0) = pack_f16x2(a0l, a1l);
                    *(uint32_t*)(hh + o1) = pack_f16x2(a2h, a3h);
                    *(uint32_t*)(hl + o1) = pack_f16x2(a2l, a3l);
                }
            }
        }
    }

    // ================= phase 2: GEMM2 (chunks 8..11) =================
    {
        const float* sB2 = (const float*)(smem + SM_B2);
        int c = 8;
        for (int nh = 0; nh < 2; nh++) {
            float acc2[2][8][4];
            #pragma unroll
            for (int mt = 0; mt < 2; mt++)
                #pragma unroll
                for (int t = 0; t < 8; t++)
                    #pragma unroll
                    for (int j = 0; j < 4; j++) acc2[mt][t][j] = 0.f;

            #pragma unroll
            for (int c2 = 0; c2 < 2; c2++, c++) {
                if (c < 11) { CP_WAIT(1); } else { CP_WAIT(0); }
                __syncthreads();             // orders H writes (c==8) and buffer reuse
                if (c + 2 < 12) issue(c + 2);
                run_fused(acc2, HHI(c2), HLO(c2), WB(c % 3), arow0, br2, a_kad, b_kad);
            }

            #pragma unroll
            for (int mt = 0; mt < 2; mt++) {
                const int r0 = 32 * wm + 16 * mt + gid;
                #pragma unroll
                for (int t = 0; t < 8; t++) {
                    const int col = nh * 256 + 64 * wn + 8 * t + 2 * tig;
                    const float c0 = sB2[col], c1 = sB2[col + 1];
                    if (r0 < rows) {
                        float2 v = { acc2[mt][t][0] + c0, acc2[mt][t][1] + c1 };
                        *(float2*)(out + (size_t)rowTok[r0] * DIM + col) = v;
                    }
                    if (r0 + 8 < rows) {
                        float2 v = { acc2[mt][t][2] + c0, acc2[mt][t][3] + c1 };
                        *(float2*)(out + (size_t)rowTok[r0 + 8] * DIM + col) = v;
                    }
                }
            }
        }
    }

    __syncthreads();
    if (tid == 0) cta_done_and_maybe_reset();
}

extern "C" void kernel_launch(void* const* d_in, const int* in_sizes, int n_in,
                              void* d_out, int out_size)
{
    const float* x   = (const float*)d_in[0];
    const float* wn0 = (const float*)d_in[2];
    const float* bn0 = (const float*)d_in[3];
    const float* wn1 = (const float*)d_in[4];
    const float* bn1 = (const float*)d_in[5];
    const float* wn2 = (const float*)d_in[6];
    const float* bn2 = (const float*)d_in[7];
    const float* w1a = (const float*)d_in[8];
    const float* b1a = (const float*)d_in[9];
    const float* w1b = (const float*)d_in[10];
    const float* b1b = (const float*)d_in[11];
    const float* w2  = (const float*)d_in[12];
    const float* b2  = (const float*)d_in[13];
    float* out = (float*)d_out;

    static_assert(SMEM_TOTAL <= 227 * 1024, "smem");
    cudaFuncSetAttribute(ffn_kernel, cudaFuncAttributeMaxDynamicSharedMemorySize, SMEM_TOTAL);

    // g_count is zero at entry: zero-initialized at module load, then re-zeroed by
    // ffn_kernel's last CTA on every launch (deterministic across graph replays).
    prep_route_kernel<<<2048, 256>>>(w1a, w1b, w2, x, wn0, bn0, wn1, bn1, wn2, bn2);
    dim3 grid(NLEAF, MAXTILES);
    ffn_kernel<<<grid, THREADS, SMEM_TOTAL>>>(b1a, b1b, b2, out);
}

// round 10
// speedup vs baseline: 2.8097x; 1.0061x over previous
#include <cuda_runtime.h>
#include <cuda_fp16.h>
#include <cstdint>

#define TOKENS   8192
#define DIM      512
#define FDIM     128
#define NLEAF    8
#define BM       64
#define MAXTILES 32
#define THREADS  512
#define TOTAL_CTAS (NLEAF * MAXTILES)

// ---------------- scratch ----------------
__device__ int g_count[NLEAF];          // zero-init at load; re-zeroed by ffn's last CTA
__device__ int g_done;                  // ffn completion counter (self-resetting)
__device__ int g_list[NLEAF * TOKENS];
__device__ __half g_x_hi[TOKENS * DIM];
__device__ __half g_x_lo[TOKENS * DIM];
// W1 transposed fp16: [leaf][n=256][k=512]; n<128 -> w1a col n, n>=128 -> w1b col n-128
__device__ __half g_w1t[NLEAF * 256 * 512];
// W2 transposed fp16: [leaf][n=512][k=128]
__device__ __half g_w2t[NLEAF * 512 * 128];

__device__ __forceinline__ uint32_t smem_u32(const void* p) {
    uint32_t a;
    asm("{ .reg .u64 t; cvta.to.shared.u64 t, %1; cvt.u32.u64 %0, t; }" : "=r"(a) : "l"(p));
    return a;
}
__device__ __forceinline__ uint32_t sw128(uint32_t off) { return off ^ ((off >> 3) & 0x70); }

__device__ __forceinline__ void split_f16(float v, __half& h, __half& l) {
    h = __float2half(v);
    l = __float2half(v - __half2float(h));
}
__device__ __forceinline__ uint32_t pack_f16x2(__half a, __half b) {
    union { __half h[2]; uint32_t u; } t;
    t.h[0] = a; t.h[1] = b;
    return t.u;
}

__device__ __forceinline__ void cpa16(uint32_t dst, const void* src) {
    asm volatile("cp.async.cg.shared.global [%0], [%1], 16;" :: "r"(dst), "l"(src) : "memory");
}
#define CP_COMMIT() asm volatile("cp.async.commit_group;" ::: "memory")
#define CP_WAIT(n)  asm volatile("cp.async.wait_group %0;" :: "n"(n) : "memory")

#define LDSM4(r, a)                                                                   \
    asm volatile("ldmatrix.sync.aligned.m8n8.x4.shared.b16 {%0,%1,%2,%3}, [%4];"     \
        : "=r"((r)[0]), "=r"((r)[1]), "=r"((r)[2]), "=r"((r)[3]) : "r"(a))

__device__ __forceinline__ void mma_f16(float* d, const uint32_t* a, uint32_t b0, uint32_t b1) {
    asm volatile(
        "mma.sync.aligned.m16n8k16.row.col.f32.f16.f16.f32 "
        "{%0,%1,%2,%3},{%4,%5,%6,%7},{%8,%9},{%0,%1,%2,%3};"
        : "+f"(d[0]), "+f"(d[1]), "+f"(d[2]), "+f"(d[3])
        : "r"(a[0]), "r"(a[1]), "r"(a[2]), "r"(a[3]), "r"(b0), "r"(b1));
}

// Fused 2-pass chunk, warp tile M16xN64: per kof -> 6 LDSM4, 16 HMMA.
__device__ __forceinline__ void run_fused(
    float acc[8][4], uint32_t AH, uint32_t AL, uint32_t B,
    uint32_t arow0, const int br[4], int a_kad, int b_kad)
{
    #pragma unroll
    for (int kof = 0; kof < 64; kof += 16) {
        uint32_t ah[4], al[4], bf[4][4];
        const uint32_t ao = sw128(arow0 + (kof + a_kad) * 2);
        LDSM4(ah, AH + ao);
        LDSM4(al, AL + ao);
        #pragma unroll
        for (int nt = 0; nt < 4; nt++)
            LDSM4(bf[nt], B + sw128((uint32_t)(br[nt] * 128 + (kof + b_kad) * 2)));
        #pragma unroll
        for (int pass = 0; pass < 2; pass++) {
            const uint32_t* af = pass ? al : ah;
            #pragma unroll
            for (int nt = 0; nt < 4; nt++) {
                mma_f16(acc[2 * nt],     af, bf[nt][0], bf[nt][1]);
                mma_f16(acc[2 * nt + 1], af, bf[nt][2], bf[nt][3]);
            }
        }
    }
}

__device__ __forceinline__ float warp_sum(float v) {
    #pragma unroll
    for (int o = 16; o > 0; o >>= 1) v += __shfl_xor_sync(0xFFFFFFFFu, v, o);
    return v;
}

// ---------------- fused prep (W transpose->fp16) + routing + X split ----------------
// blocks [0,512): W1; [512,1024): W2; [1024,2048): route (8 tokens per block). 256 threads.
__global__ void prep_route_kernel(
    const float* __restrict__ w1a, const float* __restrict__ w1b, const float* __restrict__ w2,
    const float* __restrict__ x,
    const float* __restrict__ wn0, const float* __restrict__ bn0,
    const float* __restrict__ wn1, const float* __restrict__ bn1,
    const float* __restrict__ wn2, const float* __restrict__ bn2)
{
    const int bid = blockIdx.x;
    const int tid = threadIdx.x;

    if (bid < 512) {        // ---- W1: leaf/kt/ft ----
        const int leaf = bid >> 6, rem = bid & 63, kt = rem >> 2, ft = rem & 3;
        __shared__ float ta[32][33], tb[32][33];
        {
            int r = tid >> 3, cq = tid & 7;
            size_t src = ((size_t)leaf * 512 + kt * 32 + r) * 128 + ft * 32 + cq * 4;
            float4 va = *(const float4*)(w1a + src);
            float4 vb = *(const float4*)(w1b + src);
            ta[r][cq*4+0]=va.x; ta[r][cq*4+1]=va.y; ta[r][cq*4+2]=va.z; ta[r][cq*4+3]=va.w;
            tb[r][cq*4+0]=vb.x; tb[r][cq*4+1]=vb.y; tb[r][cq*4+2]=vb.z; tb[r][cq*4+3]=vb.w;
        }
        __syncthreads();
        {
            int n = tid >> 2, kq = tid & 3;
            int side = n >> 5, fl = n & 31;
            union { __half h[8]; uint4 u; } h8;
            #pragma unroll
            for (int j = 0; j < 8; j++) {
                float v = side ? tb[kq * 8 + j][fl] : ta[kq * 8 + j][fl];
                h8.h[j] = __float2half(v);
            }
            int orow = side ? (128 + ft * 32 + fl) : (ft * 32 + fl);
            size_t off = ((size_t)leaf * 256 + orow) * 512 + kt * 32 + kq * 8;
            *(uint4*)(g_w1t + off) = h8.u;
        }
    } else if (bid < 1024) {    // ---- W2: leaf/dt/kt ----
        const int b2i = bid - 512;
        const int leaf = b2i >> 6, rem = b2i & 63, dt = rem >> 2, kt = rem & 3;
        __shared__ float t[32][33];
        {
            int r = tid >> 3, cq = tid & 7;
            size_t src = ((size_t)leaf * 128 + kt * 32 + r) * 512 + dt * 32 + cq * 4;
            float4 v = *(const float4*)(w2 + src);
            t[r][cq*4+0]=v.x; t[r][cq*4+1]=v.y; t[r][cq*4+2]=v.z; t[r][cq*4+3]=v.w;
        }
        __syncthreads();
        {
            int n = tid >> 3, kq = tid & 7;
            union { __half h[4]; uint2 u; } h4;
            #pragma unroll
            for (int j = 0; j < 4; j++) h4.h[j] = __float2half(t[kq * 4 + j][n]);
            size_t orow = ((size_t)leaf * 512 + dt * 32 + n) * 128 + kt * 32 + kq * 4;
            *(uint2*)(g_w2t + orow) = h4.u;
        }
    } else {                // ---- route: one warp per token ----
        const int gwarp = (bid - 1024) * 8 + (tid >> 5);
        const int lane  = tid & 31;

        const float4* xr4 = (const float4*)(x + (size_t)gwarp * DIM);
        float4 xv[4];
        #pragma unroll
        for (int i = 0; i < 4; i++) xv[i] = xr4[lane + i * 32];

        {
            __half* xh = g_x_hi + (size_t)gwarp * DIM;
            __half* xl = g_x_lo + (size_t)gwarp * DIM;
            #pragma unroll
            for (int i = 0; i < 4; i++) {
                float v[4] = { xv[i].x, xv[i].y, xv[i].z, xv[i].w };
                union { __half h[4]; uint2 u; } h4, l4;
                #pragma unroll
                for (int j = 0; j < 4; j++) split_f16(v[j], h4.h[j], l4.h[j]);
                *(uint2*)(xh + (lane + i * 32) * 4) = h4.u;
                *(uint2*)(xl + (lane + i * 32) * 4) = l4.u;
            }
        }

        float s = 0.f;
        #pragma unroll
        for (int i = 0; i < 4; i++) {
            int base = (lane + i * 32) * 4;
            s += xv[i].x * wn0[base + 0] + xv[i].y * wn0[base + 1]
               + xv[i].z * wn0[base + 2] + xv[i].w * wn0[base + 3];
        }
        s = warp_sum(s) + bn0[0];
        int node = (s > 0.f) ? 0 : 1;

        s = 0.f;
        #pragma unroll
        for (int i = 0; i < 4; i++) {
            int base = (lane + i * 32) * 4;
            s += xv[i].x * wn1[(base + 0) * 2 + node] + xv[i].y * wn1[(base + 1) * 2 + node]
               + xv[i].z * wn1[(base + 2) * 2 + node] + xv[i].w * wn1[(base + 3) * 2 + node];
        }
        s = warp_sum(s) + bn1[node];
        node = node * 2 + ((s > 0.f) ? 0 : 1);

        s = 0.f;
        #pragma unroll
        for (int i = 0; i < 4; i++) {
            int base = (lane + i * 32) * 4;
            s += xv[i].x * wn2[(base + 0) * 4 + node] + xv[i].y * wn2[(base + 1) * 4 + node]
               + xv[i].z * wn2[(base + 2) * 4 + node] + xv[i].w * wn2[(base + 3) * 4 + node];
        }
        s = warp_sum(s) + bn2[node];
        int leaf = node * 2 + ((s > 0.f) ? 0 : 1);

        if (lane == 0) {
            int pos = atomicAdd(&g_count[leaf], 1);
            g_list[leaf * TOKENS + pos] = gwarp;
        }
    }
}

// ---------------- SMEM layout: 3-stage pipeline ----------------
#define SM_ROWTOK  0
#define SM_B1A     256
#define SM_B1B     768
#define SM_B2      1280
#define SM_X       4096                     // 3 buf x (hi 8KB | lo 8KB) = 48KB
#define SM_W       53248                    // 3 buf x 32KB = 96KB
#define SM_H       151552                   // hi0,hi1 (16KB) then lo0,lo1 (16KB)
#define SMEM_TOTAL 184320

#define XHI(p) (sb + SM_X + (p) * 16384)
#define XLO(p) (sb + SM_X + (p) * 16384 + 8192)
#define WB(p)  (sb + SM_W + (p) * 32768)
#define HHI(k) (sb + SM_H + (k) * 8192)
#define HLO(k) (sb + SM_H + 16384 + (k) * 8192)

__device__ __forceinline__ void cta_done_and_maybe_reset() {
    int old = atomicAdd(&g_done, 1);
    if (old == TOTAL_CTAS - 1) {
        #pragma unroll
        for (int i = 0; i < NLEAF; i++) g_count[i] = 0;
        __threadfence();
        g_done = 0;
    }
}

// ---------------- fused leaf FFN: fp16 2-pass, 16 warps, M16xN64 warp tiles ----------------
__global__ void __launch_bounds__(THREADS, 1)
ffn_kernel(const float* __restrict__ b1a, const float* __restrict__ b1b,
           const float* __restrict__ b2,  float* __restrict__ out)
{
    extern __shared__ char smem[];
    const uint32_t sb = smem_u32(smem);
    const int tid  = threadIdx.x;
    const int wid  = tid >> 5;
    const int lane = tid & 31;

    const int leaf  = blockIdx.x;
    const int cnt   = g_count[leaf];
    const int start = blockIdx.y * BM;
    if (start >= cnt) {
        __syncthreads();
        if (tid == 0) cta_done_and_maybe_reset();
        return;
    }
    const int rows = min(BM, cnt - start);
    const int* list = g_list + leaf * TOKENS + start;

    int* rowTok = (int*)(smem + SM_ROWTOK);
    if (tid < BM) rowTok[tid] = list[min(tid, rows - 1)];
    {
        float* sB1a = (float*)(smem + SM_B1A);
        float* sB1b = (float*)(smem + SM_B1B);
        float* sB2  = (float*)(smem + SM_B2);
        if (tid < FDIM) { sB1a[tid] = b1a[leaf * FDIM + tid]; sB1b[tid] = b1b[leaf * FDIM + tid]; }
        if (tid < DIM)  sB2[tid] = b2[leaf * DIM + tid];
    }
    __syncthreads();

    const int wm = wid & 3;        // m-block: rows 16*wm..+15
    const int wn = wid >> 2;       // n-block 0..3
    const int gid = lane >> 2, tig = lane & 3;
    const int a_row = lane & 15;
    const int a_kad = (lane & 16) >> 1;
    const int b_row = (lane & 7) | ((lane >> 1) & 8);
    const int b_kad = lane & 8;
    const uint32_t arow0 = (uint32_t)((16 * wm + a_row) * 128);

    const int br1[4] = { 32 * wn + b_row, 32 * wn + 16 + b_row,
                         128 + 32 * wn + b_row, 128 + 32 * wn + 16 + b_row };
    const int br2[4] = { 64 * wn + b_row, 64 * wn + 16 + b_row,
                         64 * wn + 32 + b_row, 64 * wn + 48 + b_row };

    // per-thread X source row (512 threads -> 1 x 16B per half per chunk)
    const int xq = tid & 7;
    const size_t tokA = (size_t)rowTok[tid >> 3] * DIM;
    const __half* w1base = g_w1t + (size_t)leaf * 256 * DIM;
    const __half* w2base = g_w2t + (size_t)leaf * 512 * FDIM;

    auto issue = [&](int c) {
        const int p = c % 3;
        if (c < 8) {
            const int k0 = c * 64;
            {   // X hi+lo: 64 rows x 128B, one row per thread
                uint32_t so = sw128((uint32_t)((tid >> 3) * 128 + xq * 16));
                cpa16(XHI(p) + so, g_x_hi + tokA + k0 + xq * 8);
                cpa16(XLO(p) + so, g_x_lo + tokA + k0 + xq * 8);
            }
            const __half* wb = w1base + k0;
            #pragma unroll
            for (int it = 0; it < 4; it++) {           // W1: 256 rows x 128B
                int idx = tid + it * THREADS;
                int wrow = idx >> 3, q = idx & 7;
                uint32_t wo = sw128((uint32_t)(wrow * 128 + q * 16));
                cpa16(WB(p) + wo, wb + (size_t)wrow * DIM + q * 8);
            }
        } else {
            const int idx4 = c - 8, nh = idx4 >> 1, c2 = idx4 & 1;
            const __half* wb = w2base + (size_t)nh * 256 * FDIM + c2 * 64;
            #pragma unroll
            for (int it = 0; it < 4; it++) {
                int idx = tid + it * THREADS;
                int wrow = idx >> 3, q = idx & 7;
                uint32_t wo = sw128((uint32_t)(wrow * 128 + q * 16));
                cpa16(WB(p) + wo, wb + (size_t)wrow * FDIM + q * 8);
            }
        }
        CP_COMMIT();
    };

    issue(0);
    issue(1);

    // ================= phase 1: GEMM1 (chunks 0..7) =================
    {
        float acc[8][4];
        #pragma unroll
        for (int t = 0; t < 8; t++)
            #pragma unroll
            for (int j = 0; j < 4; j++) acc[t][j] = 0.f;

        for (int c = 0; c < 8; c++) {
            const int p = c % 3;
            CP_WAIT(1);                      // chunk c landed
            __syncthreads();                 // all warps past run_fused(c-1)
            issue(c + 2);                    // writes buf (c+2)%3 == (c-1)%3, now free
            run_fused(acc, XHI(p), XLO(p), WB(p), arow0, br1, a_kad, b_kad);
        }

        // epilogue1: gate (a tile nt, b tile nt+2) -> H fp16 hi/lo, packed 4B stores
        const float* sB1a = (const float*)(smem + SM_B1A);
        const float* sB1b = (const float*)(smem + SM_B1B);
        const int r0 = 16 * wm + gid;
        #pragma unroll
        for (int nt = 0; nt < 2; nt++) {
            #pragma unroll
            for (int q = 0; q < 2; q++) {
                const int f = 32 * wn + 16 * nt + 8 * q + 2 * tig;
                const float* A = acc[2 * nt + q];
                const float* G = acc[2 * (nt + 2) + q];
                const float ba0 = sB1a[f], ba1 = sB1a[f + 1];
                const float bb0 = sB1b[f], bb1 = sB1b[f + 1];
                const float h00 = (A[0] + ba0) * (G[0] + bb0);
                const float h01 = (A[1] + ba1) * (G[1] + bb1);
                const float h10 = (A[2] + ba0) * (G[2] + bb0);
                const float h11 = (A[3] + ba1) * (G[3] + bb1);
                const int kc = f >> 6, fk = f & 63;
                char* hh = smem + (HHI(kc) - sb);
                char* hl = smem + (HLO(kc) - sb);
                const uint32_t o0 = sw128((uint32_t)(r0 * 128 + fk * 2));
                const uint32_t o1 = sw128((uint32_t)((r0 + 8) * 128 + fk * 2));
                __half a0h, a0l, a1h, a1l, a2h, a2l, a3h, a3l;
                split_f16(h00, a0h, a0l);  split_f16(h01, a1h, a1l);
                split_f16(h10, a2h, a2l);  split_f16(h11, a3h, a3l);
                *(uint32_t*)(hh + o0) = pack_f16x2(a0h, a1h);
                *(uint32_t*)(hl + o0) = pack_f16x2(a0l, a1l);
                *(uint32_t*)(hh + o1) = pack_f16x2(a2h, a3h);
                *(uint32_t*)(hl + o1) = pack_f16x2(a2l, a3l);
            }
        }
    }

    // ================= phase 2: GEMM2 (chunks 8..11) =================
    {
        const float* sB2 = (const float*)(smem + SM_B2);
        int c = 8;
        for (int nh = 0; nh < 2; nh++) {
            float acc2[8][4];
            #pragma unroll
            for (int t = 0; t < 8; t++)
                #pragma unroll
                for (int j = 0; j < 4; j++) acc2[t][j] = 0.f;

            #pragma unroll
            for (int c2 = 0; c2 < 2; c2++, c++) {
                if (c < 11) { CP_WAIT(1); } else { CP_WAIT(0); }
                __syncthreads();             // orders H writes (c==8) and buffer reuse
                if (c + 2 < 12) issue(c + 2);
                run_fused(acc2, HHI(c2), HLO(c2), WB(c % 3), arow0, br2, a_kad, b_kad);
            }

            const int r0 = 16 * wm + gid;
            #pragma unroll
            for (int t = 0; t < 8; t++) {
                const int col = nh * 256 + 64 * wn + 8 * t + 2 * tig;
                const float c0 = sB2[col], c1 = sB2[col + 1];
                if (r0 < rows) {
                    float2 v = { acc2[t][0] + c0, acc2[t][1] + c1 };
                    *(float2*)(out + (size_t)rowTok[r0] * DIM + col) = v;
                }
                if (r0 + 8 < rows) {
                    float2 v = { acc2[t][2] + c0, acc2[t][3] + c1 };
                    *(float2*)(out + (size_t)rowTok[r0 + 8] * DIM + col) = v;
                }
            }
        }
    }

    __syncthreads();
    if (tid == 0) cta_done_and_maybe_reset();
}

extern "C" void kernel_launch(void* const* d_in, const int* in_sizes, int n_in,
                              void* d_out, int out_size)
{
    const float* x   = (const float*)d_in[0];
    const float* wn0 = (const float*)d_in[2];
    const float* bn0 = (const float*)d_in[3];
    const float* wn1 = (const float*)d_in[4];
    const float* bn1 = (const float*)d_in[5];
    const float* wn2 = (const float*)d_in[6];
    const float* bn2 = (const float*)d_in[7];
    const float* w1a = (const float*)d_in[8];
    const float* b1a = (const float*)d_in[9];
    const float* w1b = (const float*)d_in[10];
    const float* b1b = (const float*)d_in[11];
    const float* w2  = (const float*)d_in[12];
    const float* b2  = (const float*)d_in[13];
    float* out = (float*)d_out;

    static_assert(SMEM_TOTAL <= 227 * 1024, "smem");
    cudaFuncSetAttribute(ffn_kernel, cudaFuncAttributeMaxDynamicSharedMemorySize, SMEM_TOTAL);

    // g_count is zero at entry: zero-initialized at module load, then re-zeroed by
    // ffn_kernel's last CTA on every launch (deterministic across graph replays).
    prep_route_kernel<<<2048, 256>>>(w1a, w1b, w2, x, wn0, bn0, wn1, bn1, wn2, bn2);
    dim3 grid(NLEAF, MAXTILES);
    ffn_kernel<<<grid, THREADS, SMEM_TOTAL>>>(b1a, b1b, b2, out);
}